// round 12
// baseline (speedup 1.0000x reference)
#include <cuda_runtime.h>

#define S_LEN 128
#define B_SZ  64
#define E_DIM 512
#define PL    160
#define PD    512
#define H_DIM 1024

#define NBLK 128
#define NTHR 512

typedef unsigned long long u64;

// ---------------- persistent scratch (device globals) ----------------
__device__ __align__(16) float g_H[2][B_SZ * H_DIM];   // [buf][b][k]
__device__ __align__(16) float g_CTX[B_SZ * PD];       // [b][d]
__device__ __align__(16) float g_M[(size_t)PL * B_SZ * H_DIM];  // 42MB: M[p*64+b][k]
__device__ __align__(16) float g_PB[PL * B_SZ];        // PB[p*64+b]
__device__ unsigned int g_count;
__device__ unsigned int g_release;
__device__ unsigned int g_countC;
__device__ unsigned int g_releaseC;

// ---------------- smem layout (bytes); W/x rows padded to 260 floats ----------------
#define WPAD    260
#define WBUF_F  (48 * WPAD)            // 12480 floats / buffer
#define XBUF_F  (32 * WPAD)            // 8320 floats / buffer
#define OFF_W   0                      // 2 * 49920 = 99840
#define OFF_X   99840                  // 2 * 33280 = 66560  -> 166400
#define OFF_H   166400                 // 1024 floats = 4096
#define OFF_SC  170496                 // 160 floats = 640
#define OFF_E2  171136                 // 160 u64 = 1280
#define OFF_PART 172416                // u64[2][256] = 4096
#define OFF_ST  176512                 // 2 floats
#define OFF_MB  176528                 // 2 mbarriers
#define SMEM_SZ 176640

#define CHUNK_TX (80u * 1024u)         // 48 W rows + 32 x rows, 1KB each

// ---------------- packed f32x2 helpers ----------------
__device__ __forceinline__ void ffma2(u64& d, u64 a, u64 b) {
    asm("fma.rn.f32x2 %0, %1, %2, %0;" : "+l"(d) : "l"(a), "l"(b));
}
__device__ __forceinline__ float sum2(u64 v) {
    float lo = __int_as_float((unsigned)(v & 0xffffffffULL));
    float hi = __int_as_float((unsigned)(v >> 32));
    return lo + hi;
}

// ---------------- bulk TMA + mbarrier ----------------
__device__ __forceinline__ void bulk1k(void* sdst, const void* gsrc, unsigned mbar) {
    unsigned sd = (unsigned)__cvta_generic_to_shared(sdst);
    asm volatile(
        "cp.async.bulk.shared::cluster.global.mbarrier::complete_tx::bytes "
        "[%0], [%1], %2, [%3];"
        :: "r"(sd), "l"(gsrc), "r"(1024), "r"(mbar) : "memory");
}
__device__ __forceinline__ void mbar_init(unsigned mbar, unsigned cnt) {
    asm volatile("mbarrier.init.shared.b64 [%0], %1;" :: "r"(mbar), "r"(cnt) : "memory");
}
__device__ __forceinline__ void mbar_expect(unsigned mbar, unsigned tx) {
    asm volatile("mbarrier.arrive.expect_tx.shared.b64 _, [%0], %1;"
                 :: "r"(mbar), "r"(tx) : "memory");
}
__device__ __forceinline__ void mbar_wait(unsigned mbar, unsigned parity) {
    asm volatile(
        "{\n\t"
        ".reg .pred P1;\n\t"
        "WAIT_LOOP_%=:\n\t"
        "mbarrier.try_wait.parity.acquire.cta.shared::cta.b64 P1, [%0], %1, 0x989680;\n\t"
        "@P1 bra.uni WAIT_DONE_%=;\n\t"
        "bra.uni WAIT_LOOP_%=;\n\t"
        "WAIT_DONE_%=:\n\t"
        "}"
        :: "r"(mbar), "r"(parity) : "memory");
}

// ---------------- grid-wide epoch barrier (full, 128 blocks) ----------------
__device__ __forceinline__ void gsync(unsigned int epoch) {
    __syncthreads();
    if (threadIdx.x == 0) {
        __threadfence();
        unsigned int arrived = atomicAdd(&g_count, 1u) + 1u;
        if (arrived == (unsigned)NBLK * epoch) {
            atomicExch(&g_release, epoch);
        } else {
            while (*(volatile unsigned int*)&g_release < epoch) {
                __nanosleep(40);
            }
        }
        __threadfence();
    }
    __syncthreads();
}

// ---------------- pre-pass: h0 broadcast, barrier reset ----------------
__global__ void pre_kernel(const float* __restrict__ h_init) {
    int b = blockIdx.x;
    for (int k = threadIdx.x; k < H_DIM; k += 256)
        g_H[0][b * H_DIM + k] = h_init[k];
    if (b == 0 && threadIdx.x == 0) {
        g_count = 0u; g_release = 0u;
        g_countC = 0u; g_releaseC = 0u;
    }
}

// ---------------- precompute M[p,b,k] = sum_d post[p,b,d]*wq[d,k], PB = post.bq --------
__global__ void __launch_bounds__(512, 2) prep_M(
    const float* __restrict__ post, const float* __restrict__ wq,
    const float* __restrict__ bq)
{
    __shared__ u64 s_p[16][32];
    const int base = blockIdx.x * 16;       // 16 (p,b) pairs per block; 640 blocks
    const int tid = threadIdx.x;

    u64 acc[16];
#pragma unroll
    for (int i = 0; i < 16; i++) acc[i] = 0ull;

    for (int d0 = 0; d0 < PD; d0 += 32) {
        {
            int i = tid >> 5, dd = tid & 31;
            float v = post[(size_t)(base + i) * PD + d0 + dd];
            float2 vv = make_float2(v, v);
            s_p[i][dd] = *(u64*)&vv;
        }
        __syncthreads();
#pragma unroll 4
        for (int dd = 0; dd < 32; dd++) {
            u64 w2 = ((const u64*)(wq + (size_t)(d0 + dd) * H_DIM))[tid];
#pragma unroll
            for (int i = 0; i < 16; i++) ffma2(acc[i], w2, s_p[i][dd]);
        }
        __syncthreads();
    }
#pragma unroll
    for (int i = 0; i < 16; i++)
        ((u64*)(g_M + (size_t)(base + i) * H_DIM))[tid] = acc[i];

    int wid = tid >> 5, lane = tid & 31;
    if (wid < 16) {
        int pb = base + wid;
        float s = 0.f;
        for (int d = lane; d < PD; d += 32)
            s += post[(size_t)pb * PD + d] * bq[d];
#pragma unroll
        for (int o = 16; o > 0; o >>= 1)
            s += __shfl_xor_sync(0xffffffffu, s, o);
        if (lane == 0) g_PB[pb] = s;
    }
}

// ---------------- gates chunk prefetch (bulk TMA, warp 0 only) ----------------
// chunk map: ch 0-3 = h (whh, kc=ch); ch 4-5 = xt (wih, kc=ch-4); ch 6-7 = ctx (wih)
__device__ __forceinline__ void prefetch_bulk(
    char* smem, unsigned smem_u32, int buf, int ch, int t,
    const float* __restrict__ wih, const float* __restrict__ whh,
    const float* __restrict__ hcur, const float* __restrict__ incoming,
    int jbase, int half, int wid, int lane)
{
    if (wid != 0) return;
    unsigned mbar = smem_u32 + OFF_MB + buf * 8;
    if (lane == 0) mbar_expect(mbar, CHUNK_TX);
    __syncwarp();

    int part = (ch < 4) ? 1 : 0;
    int kc = part ? ch : (ch - 4);
    const float* W = part ? whh : wih;
    float* wd = (float*)(smem + OFF_W) + buf * WBUF_F;
    float* xd = (float*)(smem + OFF_X) + buf * XBUF_F;

#pragma unroll
    for (int i = 0; i < 3; i++) {
        int row = lane + 32 * i;        // 0..95, use < 80
        if (row < 48) {
            int g = row >> 4, r = row & 15;
            const float* src = W + ((size_t)(g * H_DIM + jbase + r)) * 1024 + kc * 256;
            bulk1k(wd + row * WPAD, src, mbar);
        } else if (row < 80) {
            int b = row - 48;
            int gb = half * 32 + b;
            const float* src;
            if (part)        src = hcur + (size_t)gb * H_DIM + kc * 256;
            else if (kc < 2) src = incoming + ((size_t)t * B_SZ + gb) * E_DIM + kc * 256;
            else             src = g_CTX + (size_t)gb * PD + (kc - 2) * 256;
            bulk1k(xd + b * WPAD, src, mbar);
        }
    }
}

// ---------------- persistent recurrent kernel ----------------
__global__ void __launch_bounds__(NTHR, 1) gru_kernel(
    const float* __restrict__ incoming,
    const float* __restrict__ post,
    const float* __restrict__ wih,
    const float* __restrict__ whh,
    const float* __restrict__ bih,
    const float* __restrict__ bhh,
    const int* __restrict__ length,
    const int* __restrict__ post_length,
    float* __restrict__ out,
    int write_last)
{
    extern __shared__ __align__(16) char smem[];
    float* s_h  = (float*)(smem + OFF_H);
    float* s_sc = (float*)(smem + OFF_SC);
    u64*   s_e2 = (u64*)(smem + OFF_E2);
    u64*   s_pt = (u64*)(smem + OFF_PART);
    float* s_st = (float*)(smem + OFF_ST);
    unsigned smem_u32 = (unsigned)__cvta_generic_to_shared(smem);

    const int tid = threadIdx.x;
    const int bx = blockIdx.x;
    const int wid = tid >> 5;
    const int lane = tid & 31;

    // gates constants: warp tile 4j x 8b
    const int g_half  = bx & 1;
    const int g_jbase = (bx >> 1) * 16;
    const int jt = wid >> 2, bt = wid & 3;
    const int j_sub = lane >> 3, bl = lane & 7;
    const int g_lb  = bt * 8 + bl;
    const int g_b   = g_half * 32 + g_lb;
    const int g_j   = g_jbase + jt * 4 + j_sub;
    const int g_len = length[g_b];

    const int is_attn = (bx < B_SZ);
    const int a_b = bx;                    // attention batch for blocks 0..63

    if (tid == 0) {
        mbar_init(smem_u32 + OFF_MB + 0, 1);
        mbar_init(smem_u32 + OFF_MB + 8, 1);
        asm volatile("fence.proxy.async.shared::cta;" ::: "memory");
    }
    __syncthreads();

    for (int t = 0; t < S_LEN; t++) {
        const float* hcur = g_H[t & 1];
        float* hnext      = g_H[(t & 1) ^ 1];

        // kick off gates chunks 0,1 (h-part; ready now)
        prefetch_bulk(smem, smem_u32, 0, 0, t, wih, whh, hcur, incoming,
                      g_jbase, g_half, wid, lane);
        prefetch_bulk(smem, smem_u32, 1, 1, t, wih, whh, hcur, incoming,
                      g_jbase, g_half, wid, lane);

        // ============ Attention: scores + softmax + context (blocks 0..63) ============
        if (is_attn) {
            const int b = a_b;
            // stage h[b] into smem (1024 floats)
            {
                const float4* src = (const float4*)(hcur + (size_t)b * H_DIM);
                float4* dst = (float4*)s_h;
                if (tid < 256) dst[tid] = src[tid];
            }
            __syncthreads();

            int pl = post_length[b];
            const ulonglong2* hh = (const ulonglong2*)s_h;
            // scores: warp per p (10 p's per warp), K=1024 lane-split
            for (int p = wid; p < PL; p += 16) {
                const ulonglong2* mm =
                    (const ulonglong2*)(g_M + ((size_t)p * B_SZ + b) * H_DIM);
                u64 a0 = 0ull, a1 = 0ull;
#pragma unroll
                for (int s = lane; s < H_DIM / 4; s += 32) {
                    ulonglong2 mv = mm[s];
                    ulonglong2 hv = hh[s];
                    ffma2(a0, mv.x, hv.x);
                    ffma2(a1, mv.y, hv.y);
                }
                float sres = sum2(a0) + sum2(a1);
#pragma unroll
                for (int o = 16; o > 0; o >>= 1)
                    sres += __shfl_xor_sync(0xffffffffu, sres, o);
                if (lane == 0)
                    s_sc[p] = (p < pl) ? (sres + g_PB[p * B_SZ + b]) : -1e30f;
            }
            __syncthreads();

            if (tid < 32) {
                float m = -1e30f;
                for (int p = tid; p < PL; p += 32) m = fmaxf(m, s_sc[p]);
#pragma unroll
                for (int o = 16; o > 0; o >>= 1)
                    m = fmaxf(m, __shfl_xor_sync(0xffffffffu, m, o));
                if (tid == 0) s_st[0] = m;
            }
            __syncthreads();
            if (tid < PL) {
                float e = __expf(s_sc[tid] - s_st[0]);
                s_sc[tid] = e;
                float2 ee = make_float2(e, e);
                s_e2[tid] = *(u64*)&ee;
            }
            __syncthreads();
            if (tid < 32) {
                float s = 0.f;
                for (int p = tid; p < PL; p += 32) s += s_sc[p];
#pragma unroll
                for (int o = 16; o > 0; o >>= 1)
                    s += __shfl_xor_sync(0xffffffffu, s, o);
                if (tid == 0) s_st[1] = 1.f / s;
            }
            __syncthreads();

            // context: all 512 threads — 2 p-groups x 256 d-pairs
            {
                int pg = tid >> 8;          // 0/1
                int dp = tid & 255;         // d-pair 0..255
                const u64* pb_ = (const u64*)post + (size_t)b * (PD / 2) + dp;
                u64 c0 = 0ull, c1 = 0ull;
                int p0 = pg * 80;
#pragma unroll 4
                for (int p = p0; p < p0 + 80; p += 2) {
                    ffma2(c0, s_e2[p],     pb_[(size_t)p * (B_SZ * PD / 2)]);
                    ffma2(c1, s_e2[p + 1], pb_[(size_t)(p + 1) * (B_SZ * PD / 2)]);
                }
                u64 c2;
                asm("add.rn.f32x2 %0, %1, %2;" : "=l"(c2) : "l"(c0), "l"(c1));
                s_pt[pg * 256 + dp] = c2;
            }
            __syncthreads();
            if (tid < 256) {
                float inv = s_st[1];
                u64 v0 = s_pt[tid], v1 = s_pt[256 + tid];
                float lo = (__int_as_float((unsigned)(v0 & 0xffffffffULL)) +
                            __int_as_float((unsigned)(v1 & 0xffffffffULL))) * inv;
                float hi = (__int_as_float((unsigned)(v0 >> 32)) +
                            __int_as_float((unsigned)(v1 >> 32))) * inv;
                *(float2*)&g_CTX[(size_t)b * PD + 2 * tid] = make_float2(lo, hi);
            }
            __syncthreads();
            // arrive on the 64-count ctx barrier
            if (tid == 0) {
                __threadfence();
                unsigned arrived = atomicAdd(&g_countC, 1u) + 1u;
                if (arrived == 64u * (unsigned)(t + 1))
                    atomicExch(&g_releaseC, (unsigned)(t + 1));
            }
        }

        // ================= Gates (bulk-TMA double buffered) =================
        {
            u64 acc[2][3];
#pragma unroll
            for (int p = 0; p < 2; p++)
#pragma unroll
                for (int g = 0; g < 3; g++) acc[p][g] = 0ull;

            for (int ch = 0; ch < 8; ch++) {
                int buf = ch & 1;
                unsigned parity = (ch >> 1) & 1;
                mbar_wait(smem_u32 + OFF_MB + buf * 8, parity);

                int part = (ch < 4) ? 1 : 0;
                const float* wbase = (const float*)(smem + OFF_W) + buf * WBUF_F;
                const float* xbase = (const float*)(smem + OFF_X) + buf * XBUF_F
                                     + g_lb * WPAD;
                const int wrow = jt * 4 + j_sub;
#pragma unroll 8
                for (int k16 = 0; k16 < 16; k16++) {
                    const ulonglong2* xp = (const ulonglong2*)(xbase + k16 * 16);
                    ulonglong2 xA = xp[0], xB = xp[1], xC = xp[2], xD = xp[3];
#pragma unroll
                    for (int g = 0; g < 3; g++) {
                        const ulonglong2* wp = (const ulonglong2*)
                            (wbase + (g * 16 + wrow) * WPAD + k16 * 16);
                        ulonglong2 wA = wp[0], wB = wp[1], wC = wp[2], wD = wp[3];
                        ffma2(acc[part][g], wA.x, xA.x);
                        ffma2(acc[part][g], wA.y, xA.y);
                        ffma2(acc[part][g], wB.x, xB.x);
                        ffma2(acc[part][g], wB.y, xB.y);
                        ffma2(acc[part][g], wC.x, xC.x);
                        ffma2(acc[part][g], wC.y, xC.y);
                        ffma2(acc[part][g], wD.x, xD.x);
                        ffma2(acc[part][g], wD.y, xD.y);
                    }
                }
                __syncthreads();
                if (ch + 2 < 8) {
                    // ctx-dependent chunks (6,7): gate warp 0 on the 64-arrive barrier
                    if (ch == 4 && wid == 0) {
                        while (*(volatile unsigned int*)&g_releaseC <
                               (unsigned)(t + 1)) {
                            __nanosleep(40);
                        }
                        __syncwarp();
                    }
                    prefetch_bulk(smem, smem_u32, buf, ch + 2, t, wih, whh,
                                  hcur, incoming, g_jbase, g_half, wid, lane);
                }
            }

            // epilogue
            float hp  = hcur[(size_t)g_b * H_DIM + g_j];
            float ir  = sum2(acc[0][0]) + bih[g_j];
            float iz  = sum2(acc[0][1]) + bih[H_DIM + g_j];
            float inn = sum2(acc[0][2]) + bih[2 * H_DIM + g_j];
            float hr  = sum2(acc[1][0]) + bhh[g_j];
            float hz  = sum2(acc[1][1]) + bhh[H_DIM + g_j];
            float hnn = sum2(acc[1][2]) + bhh[2 * H_DIM + g_j];
            float r = 1.f / (1.f + __expf(-(ir + hr)));
            float z = 1.f / (1.f + __expf(-(iz + hz)));
            float n = tanhf(inn + r * hnn);
            float hn = (1.f - z) * n + z * hp;
            if (g_len <= t) hn = 0.f;

            hnext[(size_t)g_b * H_DIM + g_j] = hn;
            out[((size_t)t * B_SZ + g_b) * H_DIM + g_j] = hn;
            if (write_last && t == S_LEN - 1) {
                out[(size_t)S_LEN * B_SZ * H_DIM + (size_t)g_b * H_DIM + g_j] = hn;
            }
        }
        gsync((unsigned)(t + 1));          // single full barrier per step
    }
}

// ---------------- launch ----------------
extern "C" void kernel_launch(void* const* d_in, const int* in_sizes, int n_in,
                              void* d_out, int out_size) {
    const float* incoming    = (const float*)d_in[0];
    const float* post        = (const float*)d_in[1];
    const float* h_init      = (const float*)d_in[2];
    const float* wih         = (const float*)d_in[3];
    const float* whh         = (const float*)d_in[4];
    const float* bih         = (const float*)d_in[5];
    const float* bhh         = (const float*)d_in[6];
    const float* wq          = (const float*)d_in[7];
    const float* bq          = (const float*)d_in[8];
    const int*   length      = (const int*)d_in[9];
    const int*   post_length = (const int*)d_in[10];
    float* out = (float*)d_out;

    int write_last = (out_size >= S_LEN * B_SZ * H_DIM + B_SZ * H_DIM) ? 1 : 0;

    cudaFuncSetAttribute(gru_kernel, cudaFuncAttributeMaxDynamicSharedMemorySize,
                         SMEM_SZ);

    pre_kernel<<<B_SZ, 256>>>(h_init);
    prep_M<<<(PL * B_SZ) / 16, 512>>>(post, wq, bq);
    gru_kernel<<<NBLK, NTHR, SMEM_SZ>>>(incoming, post, wih, whh, bih, bhh,
                                        length, post_length, out, write_last);
}

// round 13
// speedup vs baseline: 1.0005x; 1.0005x over previous
#include <cuda_runtime.h>

#define S_LEN 128
#define B_SZ  64
#define E_DIM 512
#define PL    160
#define PD    512
#define H_DIM 1024

#define NBLK 128
#define NTHR 512

typedef unsigned long long u64;

// ---------------- persistent scratch (device globals) ----------------
__device__ __align__(16) float g_H[2][B_SZ * H_DIM];   // [buf][b][k]
__device__ __align__(16) float g_CTX[B_SZ * PD];       // [b][d]
__device__ __align__(16) float g_M[(size_t)PL * B_SZ * H_DIM];  // 42MB: M[p*64+b][k]
__device__ __align__(16) float g_PB[PL * B_SZ];        // PB[p*64+b]
__device__ unsigned int g_count;
__device__ unsigned int g_release;
__device__ unsigned int g_countC;
__device__ unsigned int g_releaseC;

// ---------------- smem layout (bytes); W/x rows padded to 260 floats ----------------
#define WPAD    260
#define WBUF_F  (48 * WPAD)            // 12480 floats / buffer
#define XBUF_F  (32 * WPAD)            // 8320 floats / buffer
#define OFF_W   0                      // 2 * 49920 = 99840
#define OFF_X   99840                  // 2 * 33280 = 66560  -> 166400
#define OFF_H   166400                 // 1024 floats = 4096
#define OFF_SC  170496                 // 160 floats = 640
#define OFF_E2  171136                 // 160 u64 = 1280
#define OFF_PART 172416                // u64[2][256] = 4096
#define OFF_ST  176512                 // 2 floats
#define OFF_MB  176528                 // 2 mbarriers
#define SMEM_SZ 176640

#define CHUNK_TX (80u * 1024u)         // 48 W rows + 32 x rows, 1KB each

// ---------------- packed f32x2 helpers ----------------
__device__ __forceinline__ void ffma2(u64& d, u64 a, u64 b) {
    asm("fma.rn.f32x2 %0, %1, %2, %0;" : "+l"(d) : "l"(a), "l"(b));
}
__device__ __forceinline__ float sum2(u64 v) {
    float lo = __int_as_float((unsigned)(v & 0xffffffffULL));
    float hi = __int_as_float((unsigned)(v >> 32));
    return lo + hi;
}

// ---------------- bulk TMA + mbarrier ----------------
__device__ __forceinline__ void bulk1k(void* sdst, const void* gsrc, unsigned mbar) {
    unsigned sd = (unsigned)__cvta_generic_to_shared(sdst);
    asm volatile(
        "cp.async.bulk.shared::cluster.global.mbarrier::complete_tx::bytes "
        "[%0], [%1], %2, [%3];"
        :: "r"(sd), "l"(gsrc), "r"(1024), "r"(mbar) : "memory");
}
__device__ __forceinline__ void mbar_init(unsigned mbar, unsigned cnt) {
    asm volatile("mbarrier.init.shared.b64 [%0], %1;" :: "r"(mbar), "r"(cnt) : "memory");
}
__device__ __forceinline__ void mbar_expect(unsigned mbar, unsigned tx) {
    asm volatile("mbarrier.arrive.expect_tx.shared.b64 _, [%0], %1;"
                 :: "r"(mbar), "r"(tx) : "memory");
}
__device__ __forceinline__ void mbar_wait(unsigned mbar, unsigned parity) {
    asm volatile(
        "{\n\t"
        ".reg .pred P1;\n\t"
        "WAIT_LOOP_%=:\n\t"
        "mbarrier.try_wait.parity.acquire.cta.shared::cta.b64 P1, [%0], %1, 0x989680;\n\t"
        "@P1 bra.uni WAIT_DONE_%=;\n\t"
        "bra.uni WAIT_LOOP_%=;\n\t"
        "WAIT_DONE_%=:\n\t"
        "}"
        :: "r"(mbar), "r"(parity) : "memory");
}

// ---------------- grid-wide epoch barrier (full, 128 blocks) ----------------
__device__ __forceinline__ void gsync(unsigned int epoch) {
    __syncthreads();
    if (threadIdx.x == 0) {
        __threadfence();
        unsigned int arrived = atomicAdd(&g_count, 1u) + 1u;
        if (arrived == (unsigned)NBLK * epoch) {
            atomicExch(&g_release, epoch);
        } else {
            while (*(volatile unsigned int*)&g_release < epoch) {
                __nanosleep(40);
            }
        }
        __threadfence();
    }
    __syncthreads();
}

// ---------------- pre-pass: h0 broadcast, barrier reset ----------------
__global__ void pre_kernel(const float* __restrict__ h_init) {
    int b = blockIdx.x;
    for (int k = threadIdx.x; k < H_DIM; k += 256)
        g_H[0][b * H_DIM + k] = h_init[k];
    if (b == 0 && threadIdx.x == 0) {
        g_count = 0u; g_release = 0u;
        g_countC = 0u; g_releaseC = 0u;
    }
}

// ---------------- precompute M[p,b,k] = sum_d post[p,b,d]*wq[d,k], PB = post.bq --------
__global__ void __launch_bounds__(512, 2) prep_M(
    const float* __restrict__ post, const float* __restrict__ wq,
    const float* __restrict__ bq)
{
    __shared__ u64 s_p[16][32];
    const int base = blockIdx.x * 16;       // 16 (p,b) pairs per block; 640 blocks
    const int tid = threadIdx.x;

    u64 acc[16];
#pragma unroll
    for (int i = 0; i < 16; i++) acc[i] = 0ull;

    for (int d0 = 0; d0 < PD; d0 += 32) {
        {
            int i = tid >> 5, dd = tid & 31;
            float v = post[(size_t)(base + i) * PD + d0 + dd];
            float2 vv = make_float2(v, v);
            s_p[i][dd] = *(u64*)&vv;
        }
        __syncthreads();
#pragma unroll 4
        for (int dd = 0; dd < 32; dd++) {
            u64 w2 = ((const u64*)(wq + (size_t)(d0 + dd) * H_DIM))[tid];
#pragma unroll
            for (int i = 0; i < 16; i++) ffma2(acc[i], w2, s_p[i][dd]);
        }
        __syncthreads();
    }
#pragma unroll
    for (int i = 0; i < 16; i++)
        ((u64*)(g_M + (size_t)(base + i) * H_DIM))[tid] = acc[i];

    int wid = tid >> 5, lane = tid & 31;
    if (wid < 16) {
        int pb = base + wid;
        float s = 0.f;
        for (int d = lane; d < PD; d += 32)
            s += post[(size_t)pb * PD + d] * bq[d];
#pragma unroll
        for (int o = 16; o > 0; o >>= 1)
            s += __shfl_xor_sync(0xffffffffu, s, o);
        if (lane == 0) g_PB[pb] = s;
    }
}

// ---------------- gates chunk prefetch (bulk TMA, warp 0 only) ----------------
// chunk map: ch 0-3 = h (whh, kc=ch); ch 4-5 = xt (wih, kc=ch-4); ch 6-7 = ctx (wih)
__device__ __forceinline__ void prefetch_bulk(
    char* smem, unsigned smem_u32, int buf, int ch, int t,
    const float* __restrict__ wih, const float* __restrict__ whh,
    const float* __restrict__ hcur, const float* __restrict__ incoming,
    int jbase, int half, int wid, int lane)
{
    if (wid != 0) return;
    unsigned mbar = smem_u32 + OFF_MB + buf * 8;
    if (lane == 0) mbar_expect(mbar, CHUNK_TX);
    __syncwarp();

    int part = (ch < 4) ? 1 : 0;
    int kc = part ? ch : (ch - 4);
    const float* W = part ? whh : wih;
    float* wd = (float*)(smem + OFF_W) + buf * WBUF_F;
    float* xd = (float*)(smem + OFF_X) + buf * XBUF_F;

#pragma unroll
    for (int i = 0; i < 3; i++) {
        int row = lane + 32 * i;        // 0..95, use < 80
        if (row < 48) {
            int g = row >> 4, r = row & 15;
            const float* src = W + ((size_t)(g * H_DIM + jbase + r)) * 1024 + kc * 256;
            bulk1k(wd + row * WPAD, src, mbar);
        } else if (row < 80) {
            int b = row - 48;
            int gb = half * 32 + b;
            const float* src;
            if (part)        src = hcur + (size_t)gb * H_DIM + kc * 256;
            else if (kc < 2) src = incoming + ((size_t)t * B_SZ + gb) * E_DIM + kc * 256;
            else             src = g_CTX + (size_t)gb * PD + (kc - 2) * 256;
            bulk1k(xd + b * WPAD, src, mbar);
        }
    }
}

// ---------------- persistent recurrent kernel ----------------
__global__ void __launch_bounds__(NTHR, 1) gru_kernel(
    const float* __restrict__ incoming,
    const float* __restrict__ post,
    const float* __restrict__ wih,
    const float* __restrict__ whh,
    const float* __restrict__ bih,
    const float* __restrict__ bhh,
    const int* __restrict__ length,
    const int* __restrict__ post_length,
    float* __restrict__ out,
    int write_last)
{
    extern __shared__ __align__(16) char smem[];
    float* s_h  = (float*)(smem + OFF_H);
    float* s_sc = (float*)(smem + OFF_SC);
    u64*   s_e2 = (u64*)(smem + OFF_E2);
    u64*   s_pt = (u64*)(smem + OFF_PART);
    float* s_st = (float*)(smem + OFF_ST);
    unsigned smem_u32 = (unsigned)__cvta_generic_to_shared(smem);

    const int tid = threadIdx.x;
    const int bx = blockIdx.x;
    const int wid = tid >> 5;
    const int lane = tid & 31;

    // gates constants: warp tile 4j x 8b
    const int g_half  = bx & 1;
    const int g_jbase = (bx >> 1) * 16;
    const int jt = wid >> 2, bt = wid & 3;
    const int j_sub = lane >> 3, bl = lane & 7;
    const int g_lb  = bt * 8 + bl;
    const int g_b   = g_half * 32 + g_lb;
    const int g_j   = g_jbase + jt * 4 + j_sub;
    const int g_len = length[g_b];

    const int is_attn = (bx < B_SZ);
    const int a_b = bx;                    // attention batch for blocks 0..63

    if (tid == 0) {
        mbar_init(smem_u32 + OFF_MB + 0, 1);
        mbar_init(smem_u32 + OFF_MB + 8, 1);
        asm volatile("fence.proxy.async.shared::cta;" ::: "memory");
    }
    __syncthreads();

    for (int t = 0; t < S_LEN; t++) {
        const float* hcur = g_H[t & 1];
        float* hnext      = g_H[(t & 1) ^ 1];

        // kick off gates chunks 0,1 (h-part; ready now)
        prefetch_bulk(smem, smem_u32, 0, 0, t, wih, whh, hcur, incoming,
                      g_jbase, g_half, wid, lane);
        prefetch_bulk(smem, smem_u32, 1, 1, t, wih, whh, hcur, incoming,
                      g_jbase, g_half, wid, lane);

        // ============ Attention: scores + softmax + context (blocks 0..63) ============
        if (is_attn) {
            const int b = a_b;
            // stage h[b] into smem (1024 floats)
            {
                const float4* src = (const float4*)(hcur + (size_t)b * H_DIM);
                float4* dst = (float4*)s_h;
                if (tid < 256) dst[tid] = src[tid];
            }
            __syncthreads();

            int pl = post_length[b];
            const ulonglong2* hh = (const ulonglong2*)s_h;
            // scores: warp per p (10 p's per warp), K=1024 lane-split
            for (int p = wid; p < PL; p += 16) {
                const ulonglong2* mm =
                    (const ulonglong2*)(g_M + ((size_t)p * B_SZ + b) * H_DIM);
                u64 a0 = 0ull, a1 = 0ull;
#pragma unroll
                for (int s = lane; s < H_DIM / 4; s += 32) {
                    ulonglong2 mv = mm[s];
                    ulonglong2 hv = hh[s];
                    ffma2(a0, mv.x, hv.x);
                    ffma2(a1, mv.y, hv.y);
                }
                float sres = sum2(a0) + sum2(a1);
#pragma unroll
                for (int o = 16; o > 0; o >>= 1)
                    sres += __shfl_xor_sync(0xffffffffu, sres, o);
                if (lane == 0)
                    s_sc[p] = (p < pl) ? (sres + g_PB[p * B_SZ + b]) : -1e30f;
            }
            __syncthreads();

            if (tid < 32) {
                float m = -1e30f;
                for (int p = tid; p < PL; p += 32) m = fmaxf(m, s_sc[p]);
#pragma unroll
                for (int o = 16; o > 0; o >>= 1)
                    m = fmaxf(m, __shfl_xor_sync(0xffffffffu, m, o));
                if (tid == 0) s_st[0] = m;
            }
            __syncthreads();
            if (tid < PL) {
                float e = __expf(s_sc[tid] - s_st[0]);
                s_sc[tid] = e;
                float2 ee = make_float2(e, e);
                s_e2[tid] = *(u64*)&ee;
            }
            __syncthreads();
            if (tid < 32) {
                float s = 0.f;
                for (int p = tid; p < PL; p += 32) s += s_sc[p];
#pragma unroll
                for (int o = 16; o > 0; o >>= 1)
                    s += __shfl_xor_sync(0xffffffffu, s, o);
                if (tid == 0) s_st[1] = 1.f / s;
            }
            __syncthreads();

            // context: all 512 threads — 2 p-groups x 256 d-pairs
            {
                int pg = tid >> 8;          // 0/1
                int dp = tid & 255;         // d-pair 0..255
                const u64* pb_ = (const u64*)post + (size_t)b * (PD / 2) + dp;
                u64 c0 = 0ull, c1 = 0ull;
                int p0 = pg * 80;
#pragma unroll 4
                for (int p = p0; p < p0 + 80; p += 2) {
                    ffma2(c0, s_e2[p],     pb_[(size_t)p * (B_SZ * PD / 2)]);
                    ffma2(c1, s_e2[p + 1], pb_[(size_t)(p + 1) * (B_SZ * PD / 2)]);
                }
                u64 c2;
                asm("add.rn.f32x2 %0, %1, %2;" : "=l"(c2) : "l"(c0), "l"(c1));
                s_pt[pg * 256 + dp] = c2;
            }
            __syncthreads();
            if (tid < 256) {
                float inv = s_st[1];
                u64 v0 = s_pt[tid], v1 = s_pt[256 + tid];
                float lo = (__int_as_float((unsigned)(v0 & 0xffffffffULL)) +
                            __int_as_float((unsigned)(v1 & 0xffffffffULL))) * inv;
                float hi = (__int_as_float((unsigned)(v0 >> 32)) +
                            __int_as_float((unsigned)(v1 >> 32))) * inv;
                *(float2*)&g_CTX[(size_t)b * PD + 2 * tid] = make_float2(lo, hi);
            }
            __syncthreads();
            // arrive on the 64-count ctx barrier
            if (tid == 0) {
                __threadfence();
                unsigned arrived = atomicAdd(&g_countC, 1u) + 1u;
                if (arrived == 64u * (unsigned)(t + 1))
                    atomicExch(&g_releaseC, (unsigned)(t + 1));
            }
        }

        // ================= Gates (bulk-TMA double buffered) =================
        {
            u64 acc[2][3];
#pragma unroll
            for (int p = 0; p < 2; p++)
#pragma unroll
                for (int g = 0; g < 3; g++) acc[p][g] = 0ull;

            for (int ch = 0; ch < 8; ch++) {
                int buf = ch & 1;
                unsigned parity = (ch >> 1) & 1;
                mbar_wait(smem_u32 + OFF_MB + buf * 8, parity);

                int part = (ch < 4) ? 1 : 0;
                const float* wbase = (const float*)(smem + OFF_W) + buf * WBUF_F;
                const float* xbase = (const float*)(smem + OFF_X) + buf * XBUF_F
                                     + g_lb * WPAD;
                const int wrow = jt * 4 + j_sub;
#pragma unroll 8
                for (int k16 = 0; k16 < 16; k16++) {
                    const ulonglong2* xp = (const ulonglong2*)(xbase + k16 * 16);
                    ulonglong2 xA = xp[0], xB = xp[1], xC = xp[2], xD = xp[3];
#pragma unroll
                    for (int g = 0; g < 3; g++) {
                        const ulonglong2* wp = (const ulonglong2*)
                            (wbase + (g * 16 + wrow) * WPAD + k16 * 16);
                        ulonglong2 wA = wp[0], wB = wp[1], wC = wp[2], wD = wp[3];
                        ffma2(acc[part][g], wA.x, xA.x);
                        ffma2(acc[part][g], wA.y, xA.y);
                        ffma2(acc[part][g], wB.x, xB.x);
                        ffma2(acc[part][g], wB.y, xB.y);
                        ffma2(acc[part][g], wC.x, xC.x);
                        ffma2(acc[part][g], wC.y, xC.y);
                        ffma2(acc[part][g], wD.x, xD.x);
                        ffma2(acc[part][g], wD.y, xD.y);
                    }
                }
                __syncthreads();
                if (ch + 2 < 8) {
                    // ctx-dependent chunks (6,7): gate warp 0 on the 64-arrive barrier
                    if (ch == 4 && wid == 0) {
                        while (*(volatile unsigned int*)&g_releaseC <
                               (unsigned)(t + 1)) {
                            __nanosleep(40);
                        }
                        __syncwarp();
                    }
                    prefetch_bulk(smem, smem_u32, buf, ch + 2, t, wih, whh,
                                  hcur, incoming, g_jbase, g_half, wid, lane);
                }
            }

            // epilogue
            float hp  = hcur[(size_t)g_b * H_DIM + g_j];
            float ir  = sum2(acc[0][0]) + bih[g_j];
            float iz  = sum2(acc[0][1]) + bih[H_DIM + g_j];
            float inn = sum2(acc[0][2]) + bih[2 * H_DIM + g_j];
            float hr  = sum2(acc[1][0]) + bhh[g_j];
            float hz  = sum2(acc[1][1]) + bhh[H_DIM + g_j];
            float hnn = sum2(acc[1][2]) + bhh[2 * H_DIM + g_j];
            float r = 1.f / (1.f + __expf(-(ir + hr)));
            float z = 1.f / (1.f + __expf(-(iz + hz)));
            float n = tanhf(inn + r * hnn);
            float hn = (1.f - z) * n + z * hp;
            if (g_len <= t) hn = 0.f;

            hnext[(size_t)g_b * H_DIM + g_j] = hn;
            out[((size_t)t * B_SZ + g_b) * H_DIM + g_j] = hn;
            if (write_last && t == S_LEN - 1) {
                out[(size_t)S_LEN * B_SZ * H_DIM + (size_t)g_b * H_DIM + g_j] = hn;
            }
        }
        gsync((unsigned)(t + 1));          // single full barrier per step
    }
}

// ---------------- launch ----------------
extern "C" void kernel_launch(void* const* d_in, const int* in_sizes, int n_in,
                              void* d_out, int out_size) {
    const float* incoming    = (const float*)d_in[0];
    const float* post        = (const float*)d_in[1];
    const float* h_init      = (const float*)d_in[2];
    const float* wih         = (const float*)d_in[3];
    const float* whh         = (const float*)d_in[4];
    const float* bih         = (const float*)d_in[5];
    const float* bhh         = (const float*)d_in[6];
    const float* wq          = (const float*)d_in[7];
    const float* bq          = (const float*)d_in[8];
    const int*   length      = (const int*)d_in[9];
    const int*   post_length = (const int*)d_in[10];
    float* out = (float*)d_out;

    int write_last = (out_size >= S_LEN * B_SZ * H_DIM + B_SZ * H_DIM) ? 1 : 0;

    cudaFuncSetAttribute(gru_kernel, cudaFuncAttributeMaxDynamicSharedMemorySize,
                         SMEM_SZ);

    pre_kernel<<<B_SZ, 256>>>(h_init);
    prep_M<<<(PL * B_SZ) / 16, 512>>>(post, wq, bq);
    gru_kernel<<<NBLK, NTHR, SMEM_SZ>>>(incoming, post, wih, whh, bih, bhh,
                                        length, post_length, out, write_last);
}

// round 15
// speedup vs baseline: 1.1961x; 1.1955x over previous
#include <cuda_runtime.h>

#define S_LEN 128
#define B_SZ  64
#define E_DIM 512
#define PL    160
#define PD    512
#define H_DIM 1024

#define NBLK 128
#define NTHR 512

typedef unsigned long long u64;

// ---------------- persistent scratch (device globals) ----------------
__device__ __align__(16) float g_H[2][B_SZ * H_DIM];   // [buf][b][k]
__device__ __align__(16) float g_CTX[B_SZ * PD];       // [b][d]
__device__ __align__(16) float g_M[(size_t)PL * B_SZ * H_DIM];  // 42MB
__device__ __align__(16) float g_PB[PL * B_SZ];
// W permuted into mma B-fragment order: [NT(384)][k8(128)][lane(32)]{b0h,b1h,b0l,b1l}
__device__ __align__(16) float4 g_Wih_p[(size_t)384 * 128 * 32];
__device__ __align__(16) float4 g_Whh_p[(size_t)384 * 128 * 32];
__device__ unsigned int g_count;
__device__ unsigned int g_release;
__device__ unsigned int g_countC;
__device__ unsigned int g_releaseC;

// ---------------- smem layout (bytes) ----------------
#define WBUF_B  49152                  // 6 slots x 16 k8 x 32 lanes x 16B
#define XBUF_B  16896                  // 32 rows x 132 floats
#define OFF_W   0                      // 2 x 49152 = 98304
#define OFF_X   98304                  // 2 x 16896 = 33792 -> 132096
#define OFF_RED 132096                 // 8 x 48 x 33 floats = 50688 -> 182784
#define OFF_H   182784                 // 4096
#define OFF_SC  186880                 // 640
#define OFF_E2  187520                 // 1280
#define OFF_PT  188800                 // 4096
#define OFF_ST  192896                 // 16
#define OFF_MB  192912                 // 16
#define SMEM_SZ 193024

#define CHUNK_TX 65536u                // 48KB W + 16KB x

// ---------------- packed f32x2 helpers (attention) ----------------
__device__ __forceinline__ void ffma2(u64& d, u64 a, u64 b) {
    asm("fma.rn.f32x2 %0, %1, %2, %0;" : "+l"(d) : "l"(a), "l"(b));
}
__device__ __forceinline__ float sum2(u64 v) {
    float lo = __int_as_float((unsigned)(v & 0xffffffffULL));
    float hi = __int_as_float((unsigned)(v >> 32));
    return lo + hi;
}

// ---------------- tf32 helpers ----------------
__device__ __forceinline__ unsigned tf32h(float x) {
    unsigned r; asm("cvt.rna.tf32.f32 %0, %1;" : "=r"(r) : "f"(x)); return r;
}
__device__ __forceinline__ void mma8(float (&c)[4],
    unsigned a0, unsigned a1, unsigned a2, unsigned a3,
    unsigned b0, unsigned b1)
{
    asm volatile(
        "mma.sync.aligned.m16n8k8.row.col.f32.tf32.tf32.f32 "
        "{%0,%1,%2,%3}, {%4,%5,%6,%7}, {%8,%9}, {%0,%1,%2,%3};"
        : "+f"(c[0]), "+f"(c[1]), "+f"(c[2]), "+f"(c[3])
        : "r"(a0), "r"(a1), "r"(a2), "r"(a3), "r"(b0), "r"(b1));
}

// ---------------- bulk TMA + mbarrier ----------------
__device__ __forceinline__ void bulkN(void* sdst, const void* gsrc,
                                      unsigned bytes, unsigned mbar) {
    unsigned sd = (unsigned)__cvta_generic_to_shared(sdst);
    asm volatile(
        "cp.async.bulk.shared::cluster.global.mbarrier::complete_tx::bytes "
        "[%0], [%1], %2, [%3];"
        :: "r"(sd), "l"(gsrc), "r"(bytes), "r"(mbar) : "memory");
}
__device__ __forceinline__ void mbar_init(unsigned mbar, unsigned cnt) {
    asm volatile("mbarrier.init.shared.b64 [%0], %1;" :: "r"(mbar), "r"(cnt) : "memory");
}
__device__ __forceinline__ void mbar_expect(unsigned mbar, unsigned tx) {
    asm volatile("mbarrier.arrive.expect_tx.shared.b64 _, [%0], %1;"
                 :: "r"(mbar), "r"(tx) : "memory");
}
__device__ __forceinline__ void mbar_wait(unsigned mbar, unsigned parity) {
    asm volatile(
        "{\n\t"
        ".reg .pred P1;\n\t"
        "WAIT_LOOP_%=:\n\t"
        "mbarrier.try_wait.parity.acquire.cta.shared::cta.b64 P1, [%0], %1, 0x989680;\n\t"
        "@P1 bra.uni WAIT_DONE_%=;\n\t"
        "bra.uni WAIT_LOOP_%=;\n\t"
        "WAIT_DONE_%=:\n\t"
        "}"
        :: "r"(mbar), "r"(parity) : "memory");
}

// ---------------- grid-wide epoch barrier ----------------
__device__ __forceinline__ void gsync(unsigned int epoch) {
    __syncthreads();
    if (threadIdx.x == 0) {
        __threadfence();
        unsigned int arrived = atomicAdd(&g_count, 1u) + 1u;
        if (arrived == (unsigned)NBLK * epoch) {
            atomicExch(&g_release, epoch);
        } else {
            while (*(volatile unsigned int*)&g_release < epoch) {
                __nanosleep(40);
            }
        }
        __threadfence();
    }
    __syncthreads();
}

// ---------------- pre-pass ----------------
__global__ void pre_kernel(const float* __restrict__ h_init) {
    int b = blockIdx.x;
    for (int k = threadIdx.x; k < H_DIM; k += 256)
        g_H[0][b * H_DIM + k] = h_init[k];
    if (b == 0 && threadIdx.x == 0) {
        g_count = 0u; g_release = 0u;
        g_countC = 0u; g_releaseC = 0u;
    }
}

// ---------------- W split-tf32 + permute precompute ----------------
__global__ void prep_W(const float* __restrict__ wih,
                       const float* __restrict__ whh) {
    size_t gid = (size_t)blockIdx.x * 256 + threadIdx.x;
    int lane = (int)(gid & 31);
    size_t rest = gid >> 5;
    int k8 = (int)(rest & 127);
    rest >>= 7;
    int NT = (int)(rest % 384);
    int mat = (int)(rest / 384);
    const float* W = mat ? whh : wih;
    float4* dst = mat ? g_Whh_p : g_Wih_p;
    int R = NT * 8 + (lane >> 2);
    int k = k8 * 8 + (lane & 3);
    float w0 = W[(size_t)R * 1024 + k];
    float w1 = W[(size_t)R * 1024 + k + 4];
    unsigned h0 = tf32h(w0), h1 = tf32h(w1);
    unsigned l0 = tf32h(w0 - __uint_as_float(h0));
    unsigned l1 = tf32h(w1 - __uint_as_float(h1));
    dst[((size_t)NT * 128 + k8) * 32 + lane] =
        make_float4(__uint_as_float(h0), __uint_as_float(h1),
                    __uint_as_float(l0), __uint_as_float(l1));
}

// ---------------- precompute M = post @ wq (scores operand), PB = post.bq ----------
__global__ void __launch_bounds__(512, 2) prep_M(
    const float* __restrict__ post, const float* __restrict__ wq,
    const float* __restrict__ bq)
{
    __shared__ u64 s_p[16][32];
    const int base = blockIdx.x * 16;
    const int tid = threadIdx.x;
    u64 acc[16];
#pragma unroll
    for (int i = 0; i < 16; i++) acc[i] = 0ull;
    for (int d0 = 0; d0 < PD; d0 += 32) {
        {
            int i = tid >> 5, dd = tid & 31;
            float v = post[(size_t)(base + i) * PD + d0 + dd];
            float2 vv = make_float2(v, v);
            s_p[i][dd] = *(u64*)&vv;
        }
        __syncthreads();
#pragma unroll 4
        for (int dd = 0; dd < 32; dd++) {
            u64 w2 = ((const u64*)(wq + (size_t)(d0 + dd) * H_DIM))[tid];
#pragma unroll
            for (int i = 0; i < 16; i++) ffma2(acc[i], w2, s_p[i][dd]);
        }
        __syncthreads();
    }
#pragma unroll
    for (int i = 0; i < 16; i++)
        ((u64*)(g_M + (size_t)(base + i) * H_DIM))[tid] = acc[i];
    int wid = tid >> 5, lane = tid & 31;
    if (wid < 16) {
        int pb = base + wid;
        float s = 0.f;
        for (int d = lane; d < PD; d += 32)
            s += post[(size_t)pb * PD + d] * bq[d];
#pragma unroll
        for (int o = 16; o > 0; o >>= 1)
            s += __shfl_xor_sync(0xffffffffu, s, o);
        if (lane == 0) g_PB[pb] = s;
    }
}

// ---------------- gates chunk prefetch (bulk TMA, warp 0) ----------------
// ch 0-7: h part (Whh_p, x=h, kc=ch); ch 8-15: i part (Wih_p, kc=ch-8; x: kc<4 xt else ctx)
__device__ __forceinline__ void prefetch_mma(
    char* smem, unsigned smem_u32, int buf, int ch, int t,
    const float* __restrict__ hcur, const float* __restrict__ incoming,
    int jbase, int half, int wid, int lane)
{
    if (wid != 0) return;
    unsigned mbar = smem_u32 + OFF_MB + buf * 8;
    if (lane == 0) mbar_expect(mbar, CHUNK_TX);
    __syncwarp();

    int part_h = (ch < 8);
    int kc = part_h ? ch : (ch - 8);
    const float4* Wp = part_h ? g_Whh_p : g_Wih_p;
    char* wd = smem + OFF_W + buf * WBUF_B;
    char* xd = smem + OFF_X + buf * XBUF_B;

    if (lane < 6) {   // 6 W slots, 8KB each
        int g = lane >> 1, sl = lane & 1;
        int NT = g * 128 + (jbase >> 3) + sl;
        bulkN(wd + lane * 8192, Wp + ((size_t)NT * 128 + kc * 16) * 32, 8192, mbar);
    }
    {                 // 32 x rows, 512B each
        int gb = half * 32 + lane;
        const float* src;
        if (part_h)      src = hcur + (size_t)gb * H_DIM + kc * 128;
        else if (kc < 4) src = incoming + ((size_t)t * B_SZ + gb) * E_DIM + kc * 128;
        else             src = g_CTX + (size_t)gb * PD + (kc - 4) * 128;
        bulkN(xd + lane * 528, src, 512, mbar);
    }
}

// ---------------- one chunk of split-tf32 MMA ----------------
__device__ __forceinline__ void chunk_mma(
    const float* s_x_, const float4* s_w_, int ks, int mt, int nt, int lane,
    float (&acc)[3][4])
{
    const int r0 = mt * 16 + (lane >> 2);
#pragma unroll
    for (int k8i = 0; k8i < 4; k8i++) {
        int kl = (ks * 4 + k8i) * 8 + (lane & 3);
        float x00 = s_x_[r0 * 132 + kl];          // (row, k)
        float x01 = s_x_[r0 * 132 + kl + 4];      // (row, k+4)
        float x10 = s_x_[(r0 + 8) * 132 + kl];    // (row+8, k)
        float x11 = s_x_[(r0 + 8) * 132 + kl + 4];
        // A frag order: a0=(r,k) a1=(r+8,k) a2=(r,k+4) a3=(r+8,k+4)
        unsigned ah0 = tf32h(x00), ah1 = tf32h(x10), ah2 = tf32h(x01), ah3 = tf32h(x11);
        unsigned al0 = tf32h(x00 - __uint_as_float(ah0));
        unsigned al1 = tf32h(x10 - __uint_as_float(ah1));
        unsigned al2 = tf32h(x01 - __uint_as_float(ah2));
        unsigned al3 = tf32h(x11 - __uint_as_float(ah3));
#pragma unroll
        for (int i = 0; i < 3; i++) {
            float4 wv = s_w_[((size_t)((nt * 3 + i) * 16 + ks * 4 + k8i)) * 32 + lane];
            unsigned bh0 = __float_as_uint(wv.x), bh1 = __float_as_uint(wv.y);
            unsigned bl0 = __float_as_uint(wv.z), bl1 = __float_as_uint(wv.w);
            mma8(acc[i], ah0, ah1, ah2, ah3, bh0, bh1);
            mma8(acc[i], ah0, ah1, ah2, ah3, bl0, bl1);
            mma8(acc[i], al0, al1, al2, al3, bh0, bh1);
        }
    }
}

// ---------------- persistent recurrent kernel ----------------
__global__ void __launch_bounds__(NTHR, 1) gru_kernel(
    const float* __restrict__ incoming,
    const float* __restrict__ post,
    const float* __restrict__ bih,
    const float* __restrict__ bhh,
    const int* __restrict__ length,
    const int* __restrict__ post_length,
    float* __restrict__ out,
    int write_last)
{
    extern __shared__ __align__(16) char smem[];
    float* s_red = (float*)(smem + OFF_RED);   // [8][48][33]
    float* s_h  = (float*)(smem + OFF_H);
    float* s_sc = (float*)(smem + OFF_SC);
    u64*   s_e2 = (u64*)(smem + OFF_E2);
    u64*   s_pt = (u64*)(smem + OFF_PT);
    float* s_st = (float*)(smem + OFF_ST);
    unsigned smem_u32 = (unsigned)__cvta_generic_to_shared(smem);

    const int tid = threadIdx.x;
    const int bx = blockIdx.x;
    const int wid = tid >> 5;
    const int lane = tid & 31;

    // gates constants
    const int g_half  = bx & 1;
    const int g_jbase = (bx >> 1) * 16;
    const int ks = wid & 3;                    // k-split quarter
    const int mt = (wid >> 2) & 1;             // b tile (16)
    const int nt = wid >> 3;                   // row tile (24)
    // epilogue mapping: thread = (j, b)
    const int e_j = tid >> 5;                  // 0..15
    const int e_b = tid & 31;
    const int e_gb = g_half * 32 + e_b;
    const int e_gj = g_jbase + e_j;
    const int e_len = length[e_gb];

    const int is_attn = (bx < B_SZ);
    const int a_b = bx;

    if (tid == 0) {
        mbar_init(smem_u32 + OFF_MB + 0, 1);
        mbar_init(smem_u32 + OFF_MB + 8, 1);
        asm volatile("fence.proxy.async.shared::cta;" ::: "memory");
    }
    __syncthreads();

    for (int t = 0; t < S_LEN; t++) {
        const float* hcur = g_H[t & 1];
        float* hnext      = g_H[(t & 1) ^ 1];

        prefetch_mma(smem, smem_u32, 0, 0, t, hcur, incoming, g_jbase, g_half, wid, lane);
        prefetch_mma(smem, smem_u32, 1, 1, t, hcur, incoming, g_jbase, g_half, wid, lane);

        // ============ Attention (blocks 0..63): scores + softmax + context ============
        if (is_attn) {
            const int b = a_b;
            {
                const float4* src = (const float4*)(hcur + (size_t)b * H_DIM);
                float4* dst = (float4*)s_h;
                if (tid < 256) dst[tid] = src[tid];
            }
            __syncthreads();

            int pl = post_length[b];
            const ulonglong2* hh = (const ulonglong2*)s_h;
            for (int p = wid; p < PL; p += 16) {
                const ulonglong2* mm =
                    (const ulonglong2*)(g_M + ((size_t)p * B_SZ + b) * H_DIM);
                u64 a0 = 0ull, a1 = 0ull;
#pragma unroll
                for (int s = lane; s < H_DIM / 4; s += 32) {
                    ulonglong2 mv = mm[s];
                    ulonglong2 hv = hh[s];
                    ffma2(a0, mv.x, hv.x);
                    ffma2(a1, mv.y, hv.y);
                }
                float sres = sum2(a0) + sum2(a1);
#pragma unroll
                for (int o = 16; o > 0; o >>= 1)
                    sres += __shfl_xor_sync(0xffffffffu, sres, o);
                if (lane == 0)
                    s_sc[p] = (p < pl) ? (sres + g_PB[p * B_SZ + b]) : -1e30f;
            }
            __syncthreads();

            if (tid < 32) {
                float m = -1e30f;
                for (int p = tid; p < PL; p += 32) m = fmaxf(m, s_sc[p]);
#pragma unroll
                for (int o = 16; o > 0; o >>= 1)
                    m = fmaxf(m, __shfl_xor_sync(0xffffffffu, m, o));
                if (tid == 0) s_st[0] = m;
            }
            __syncthreads();
            if (tid < PL) {
                float e = __expf(s_sc[tid] - s_st[0]);
                s_sc[tid] = e;
                float2 ee = make_float2(e, e);
                s_e2[tid] = *(u64*)&ee;
            }
            __syncthreads();
            if (tid < 32) {
                float s = 0.f;
                for (int p = tid; p < PL; p += 32) s += s_sc[p];
#pragma unroll
                for (int o = 16; o > 0; o >>= 1)
                    s += __shfl_xor_sync(0xffffffffu, s, o);
                if (tid == 0) s_st[1] = 1.f / s;
            }
            __syncthreads();

            {
                int pg = tid >> 8;
                int dp = tid & 255;
                const u64* pb_ = (const u64*)post + (size_t)b * (PD / 2) + dp;
                u64 c0 = 0ull, c1 = 0ull;
                int p0 = pg * 80;
#pragma unroll 4
                for (int p = p0; p < p0 + 80; p += 2) {
                    ffma2(c0, s_e2[p],     pb_[(size_t)p * (B_SZ * PD / 2)]);
                    ffma2(c1, s_e2[p + 1], pb_[(size_t)(p + 1) * (B_SZ * PD / 2)]);
                }
                u64 c2;
                asm("add.rn.f32x2 %0, %1, %2;" : "=l"(c2) : "l"(c0), "l"(c1));
                s_pt[pg * 256 + dp] = c2;
            }
            __syncthreads();
            if (tid < 256) {
                float inv = s_st[1];
                u64 v0 = s_pt[tid], v1 = s_pt[256 + tid];
                float lo = (__int_as_float((unsigned)(v0 & 0xffffffffULL)) +
                            __int_as_float((unsigned)(v1 & 0xffffffffULL))) * inv;
                float hi = (__int_as_float((unsigned)(v0 >> 32)) +
                            __int_as_float((unsigned)(v1 >> 32))) * inv;
                *(float2*)&g_CTX[(size_t)b * PD + 2 * tid] = make_float2(lo, hi);
            }
            __syncthreads();
            if (tid == 0) {
                __threadfence();
                unsigned arrived = atomicAdd(&g_countC, 1u) + 1u;
                if (arrived == 64u * (unsigned)(t + 1))
                    atomicExch(&g_releaseC, (unsigned)(t + 1));
            }
        }

        // ================= Gates: split-tf32 mma, TMA double-buffered =================
        {
            float accH[3][4], accI[3][4];
#pragma unroll
            for (int i = 0; i < 3; i++)
#pragma unroll
                for (int r = 0; r < 4; r++) { accH[i][r] = 0.f; accI[i][r] = 0.f; }

            for (int ch = 0; ch < 16; ch++) {
                int buf = ch & 1;
                unsigned parity = (ch >> 1) & 1;
                mbar_wait(smem_u32 + OFF_MB + buf * 8, parity);

                const float* s_x_ = (const float*)(smem + OFF_X + buf * XBUF_B);
                const float4* s_w_ = (const float4*)(smem + OFF_W + buf * WBUF_B);
                if (ch < 8) chunk_mma(s_x_, s_w_, ks, mt, nt, lane, accH);
                else        chunk_mma(s_x_, s_w_, ks, mt, nt, lane, accI);
                __syncthreads();

                if (ch + 2 < 16) {
                    if (ch == 10 && wid == 0) {   // ctx ready before chunk 12 prefetch
                        while (*(volatile unsigned int*)&g_releaseC <
                               (unsigned)(t + 1)) {
                            __nanosleep(40);
                        }
                        __syncwarp();
                    }
                    prefetch_mma(smem, smem_u32, buf, ch + 2, t, hcur, incoming,
                                 g_jbase, g_half, wid, lane);
                }
            }

            // ---- k-split reduction through smem ----
#pragma unroll
            for (int i = 0; i < 3; i++)
#pragma unroll
                for (int r = 0; r < 4; r++) {
                    int row = (nt * 3 + i) * 8 + (lane & 3) * 2 + (r & 1);
                    int bb  = mt * 16 + (lane >> 2) + (r >> 1) * 8;
                    s_red[((ks * 2 + 0) * 48 + row) * 33 + bb] = accI[i][r];
                    s_red[((ks * 2 + 1) * 48 + row) * 33 + bb] = accH[i][r];
                }
            __syncthreads();

            // ---- epilogue: thread = (j, b) ----
            float gi_[3], gh_[3];
#pragma unroll
            for (int g = 0; g < 3; g++) {
                int row = (g * 2 + (e_j >> 3)) * 8 + (e_j & 7);
                float si = 0.f, sh = 0.f;
#pragma unroll
                for (int kk = 0; kk < 4; kk++) {
                    si += s_red[((kk * 2 + 0) * 48 + row) * 33 + e_b];
                    sh += s_red[((kk * 2 + 1) * 48 + row) * 33 + e_b];
                }
                gi_[g] = si;
                gh_[g] = sh;
            }
            float hp  = hcur[(size_t)e_gb * H_DIM + e_gj];
            float ir  = gi_[0] + bih[e_gj];
            float iz  = gi_[1] + bih[H_DIM + e_gj];
            float inn = gi_[2] + bih[2 * H_DIM + e_gj];
            float hr  = gh_[0] + bhh[e_gj];
            float hz  = gh_[1] + bhh[H_DIM + e_gj];
            float hnn = gh_[2] + bhh[2 * H_DIM + e_gj];
            float r = 1.f / (1.f + __expf(-(ir + hr)));
            float z = 1.f / (1.f + __expf(-(iz + hz)));
            float n = tanhf(inn + r * hnn);
            float hn = (1.f - z) * n + z * hp;
            if (e_len <= t) hn = 0.f;

            hnext[(size_t)e_gb * H_DIM + e_gj] = hn;
            out[((size_t)t * B_SZ + e_gb) * H_DIM + e_gj] = hn;
            if (write_last && t == S_LEN - 1) {
                out[(size_t)S_LEN * B_SZ * H_DIM + (size_t)e_gb * H_DIM + e_gj] = hn;
            }
        }
        gsync((unsigned)(t + 1));
    }
}

// ---------------- launch ----------------
extern "C" void kernel_launch(void* const* d_in, const int* in_sizes, int n_in,
                              void* d_out, int out_size) {
    const float* incoming    = (const float*)d_in[0];
    const float* post        = (const float*)d_in[1];
    const float* h_init      = (const float*)d_in[2];
    const float* wih         = (const float*)d_in[3];
    const float* whh         = (const float*)d_in[4];
    const float* bih         = (const float*)d_in[5];
    const float* bhh         = (const float*)d_in[6];
    const float* wq          = (const float*)d_in[7];
    const float* bq          = (const float*)d_in[8];
    const int*   length      = (const int*)d_in[9];
    const int*   post_length = (const int*)d_in[10];
    float* out = (float*)d_out;

    int write_last = (out_size >= S_LEN * B_SZ * H_DIM + B_SZ * H_DIM) ? 1 : 0;

    cudaFuncSetAttribute(gru_kernel, cudaFuncAttributeMaxDynamicSharedMemorySize,
                         SMEM_SZ);

    pre_kernel<<<B_SZ, 256>>>(h_init);
    prep_W<<<(2 * 384 * 128 * 32) / 256, 256>>>(wih, whh);
    prep_M<<<(PL * B_SZ) / 16, 512>>>(post, wq, bq);
    gru_kernel<<<NBLK, NTHR, SMEM_SZ>>>(incoming, post, bih, bhh,
                                        length, post_length, out, write_last);
}

// round 16
// speedup vs baseline: 1.5056x; 1.2587x over previous
#include <cuda_runtime.h>
#include <cuda_bf16.h>

#define S_LEN 128
#define B_SZ  64
#define E_DIM 512
#define PL    160
#define PD    512
#define H_DIM 1024

#define NBLK 128
#define NTHR 512

typedef unsigned long long u64;

// ---------------- persistent scratch (device globals) ----------------
__device__ __align__(16) float g_H[2][B_SZ * H_DIM];     // fp32 h (attention + epilogue)
__device__ __align__(16) u64 g_Hb[2][B_SZ * H_DIM / 2];  // split-bf16 h (gates)
__device__ __align__(16) u64 g_CTXb[B_SZ * PD / 2];      // split-bf16 ctx
__device__ __align__(16) u64 g_INCb[(size_t)S_LEN * B_SZ * E_DIM / 2];
__device__ __align__(16) float g_M[(size_t)PL * B_SZ * H_DIM];  // 42MB
__device__ __align__(16) float g_PB[PL * B_SZ];
// W packed bf16-split B-fragments: [NT(384)][k16(64)][lane(32)] {b0m,b1m,b0r,b1r}
__device__ __align__(16) uint4 g_Wih_p[(size_t)384 * 64 * 32];
__device__ __align__(16) uint4 g_Whh_p[(size_t)384 * 64 * 32];
__device__ unsigned int g_count;
__device__ unsigned int g_release;
__device__ unsigned int g_countC;
__device__ unsigned int g_releaseC;

// ---------------- smem layout (bytes) ----------------
#define WBUF_B  24576                  // 6 slots x 4KB
#define XROW_U64 68                    // 544B row stride (conflict-free LDS.64)
#define XBUF_B  17408                  // 32 rows x 544B
#define OFF_W   0                      // 2 x 24576 = 49152
#define OFF_X   49152                  // 2 x 17408 = 34816 -> 83968
#define OFF_RED 83968                  // 8 x 48 x 33 floats = 50688 -> 134656
#define OFF_H   134656                 // 4096
#define OFF_SC  138752                 // 640
#define OFF_E2  139392                 // 1280
#define OFF_PT  140672                 // 4096
#define OFF_ST  144768                 // 16
#define OFF_MB  144784                 // 16
#define SMEM_SZ 144896

#define CHUNK_TX 40960u                // 6*4096 W + 32*512 x

// ---------------- packed f32x2 helpers (attention) ----------------
__device__ __forceinline__ void ffma2(u64& d, u64 a, u64 b) {
    asm("fma.rn.f32x2 %0, %1, %2, %0;" : "+l"(d) : "l"(a), "l"(b));
}
__device__ __forceinline__ float sum2(u64 v) {
    float lo = __int_as_float((unsigned)(v & 0xffffffffULL));
    float hi = __int_as_float((unsigned)(v >> 32));
    return lo + hi;
}

// ---------------- bf16 split helpers ----------------
// pack 2 elems (a = elem k -> low, b = elem k+1 -> high): {main bf16x2, resid bf16x2}
__device__ __forceinline__ u64 split2(float a, float b) {
    unsigned mp;
    asm("cvt.rn.bf16x2.f32 %0, %1, %2;" : "=r"(mp) : "f"(b), "f"(a));
    float ra = a - __uint_as_float(mp << 16);
    float rb = b - __uint_as_float(mp & 0xffff0000u);
    unsigned rp;
    asm("cvt.rn.bf16x2.f32 %0, %1, %2;" : "=r"(rp) : "f"(rb), "f"(ra));
    return ((u64)rp << 32) | (u64)mp;
}
__device__ __forceinline__ void mma16(float (&c)[4],
    unsigned a0, unsigned a1, unsigned a2, unsigned a3,
    unsigned b0, unsigned b1)
{
    asm volatile(
        "mma.sync.aligned.m16n8k16.row.col.f32.bf16.bf16.f32 "
        "{%0,%1,%2,%3}, {%4,%5,%6,%7}, {%8,%9}, {%0,%1,%2,%3};"
        : "+f"(c[0]), "+f"(c[1]), "+f"(c[2]), "+f"(c[3])
        : "r"(a0), "r"(a1), "r"(a2), "r"(a3), "r"(b0), "r"(b1));
}

// ---------------- bulk TMA + mbarrier ----------------
__device__ __forceinline__ void bulkN(void* sdst, const void* gsrc,
                                      unsigned bytes, unsigned mbar) {
    unsigned sd = (unsigned)__cvta_generic_to_shared(sdst);
    asm volatile(
        "cp.async.bulk.shared::cluster.global.mbarrier::complete_tx::bytes "
        "[%0], [%1], %2, [%3];"
        :: "r"(sd), "l"(gsrc), "r"(bytes), "r"(mbar) : "memory");
}
__device__ __forceinline__ void mbar_init(unsigned mbar, unsigned cnt) {
    asm volatile("mbarrier.init.shared.b64 [%0], %1;" :: "r"(mbar), "r"(cnt) : "memory");
}
__device__ __forceinline__ void mbar_expect(unsigned mbar, unsigned tx) {
    asm volatile("mbarrier.arrive.expect_tx.shared.b64 _, [%0], %1;"
                 :: "r"(mbar), "r"(tx) : "memory");
}
__device__ __forceinline__ void mbar_wait(unsigned mbar, unsigned parity) {
    asm volatile(
        "{\n\t"
        ".reg .pred P1;\n\t"
        "WAIT_LOOP_%=:\n\t"
        "mbarrier.try_wait.parity.acquire.cta.shared::cta.b64 P1, [%0], %1, 0x989680;\n\t"
        "@P1 bra.uni WAIT_DONE_%=;\n\t"
        "bra.uni WAIT_LOOP_%=;\n\t"
        "WAIT_DONE_%=:\n\t"
        "}"
        :: "r"(mbar), "r"(parity) : "memory");
}

// ---------------- grid-wide epoch barrier ----------------
__device__ __forceinline__ void gsync(unsigned int epoch) {
    __syncthreads();
    if (threadIdx.x == 0) {
        __threadfence();
        unsigned int arrived = atomicAdd(&g_count, 1u) + 1u;
        if (arrived == (unsigned)NBLK * epoch) {
            atomicExch(&g_release, epoch);
        } else {
            while (*(volatile unsigned int*)&g_release < epoch) {
                __nanosleep(40);
            }
        }
        __threadfence();
    }
    __syncthreads();
}

// ---------------- pre-pass: h0 broadcast (fp32 + split), incoming split ----------------
__global__ void pre_kernel(const float* __restrict__ h_init) {
    int b = blockIdx.x;
    for (int k = threadIdx.x; k < H_DIM; k += 256)
        g_H[0][b * H_DIM + k] = h_init[k];
    for (int k2 = threadIdx.x; k2 < H_DIM / 2; k2 += 256)
        g_Hb[0][b * (H_DIM / 2) + k2] = split2(h_init[2 * k2], h_init[2 * k2 + 1]);
    if (b == 0 && threadIdx.x == 0) {
        g_count = 0u; g_release = 0u;
        g_countC = 0u; g_releaseC = 0u;
    }
}

__global__ void prep_inc(const float* __restrict__ incoming) {
    int t = blockIdx.x;
    for (int idx = threadIdx.x; idx < B_SZ * E_DIM / 2; idx += 256) {
        const float* src = incoming + (size_t)t * B_SZ * E_DIM + 2 * idx;
        g_INCb[(size_t)t * (B_SZ * E_DIM / 2) + idx] = split2(src[0], src[1]);
    }
}

// ---------------- W bf16-split B-fragment precompute ----------------
__global__ void prep_W(const float* __restrict__ wih,
                       const float* __restrict__ whh) {
    size_t gid = (size_t)blockIdx.x * 256 + threadIdx.x;
    int lane = (int)(gid & 31);
    size_t rest = gid >> 5;
    int k16 = (int)(rest & 63);
    rest >>= 6;
    int NT = (int)(rest % 384);
    int mat = (int)(rest / 384);
    const float* W = mat ? whh : wih;
    uint4* dst = mat ? g_Whh_p : g_Wih_p;
    int R = NT * 8 + (lane >> 2);
    int k0 = k16 * 16 + (lane & 3) * 2;
    float w00 = W[(size_t)R * 1024 + k0];
    float w01 = W[(size_t)R * 1024 + k0 + 1];
    float w10 = W[(size_t)R * 1024 + k0 + 8];
    float w11 = W[(size_t)R * 1024 + k0 + 9];
    u64 s0 = split2(w00, w01);
    u64 s1 = split2(w10, w11);
    uint4 v;
    v.x = (unsigned)s0;          // b0 main
    v.y = (unsigned)s1;          // b1 main
    v.z = (unsigned)(s0 >> 32);  // b0 resid
    v.w = (unsigned)(s1 >> 32);  // b1 resid
    dst[((size_t)NT * 64 + k16) * 32 + lane] = v;
}

// ---------------- precompute M = post @ wq, PB = post.bq ----------------
__global__ void __launch_bounds__(512, 2) prep_M(
    const float* __restrict__ post, const float* __restrict__ wq,
    const float* __restrict__ bq)
{
    __shared__ u64 s_p[16][32];
    const int base = blockIdx.x * 16;
    const int tid = threadIdx.x;
    u64 acc[16];
#pragma unroll
    for (int i = 0; i < 16; i++) acc[i] = 0ull;
    for (int d0 = 0; d0 < PD; d0 += 32) {
        {
            int i = tid >> 5, dd = tid & 31;
            float v = post[(size_t)(base + i) * PD + d0 + dd];
            float2 vv = make_float2(v, v);
            s_p[i][dd] = *(u64*)&vv;
        }
        __syncthreads();
#pragma unroll 4
        for (int dd = 0; dd < 32; dd++) {
            u64 w2 = ((const u64*)(wq + (size_t)(d0 + dd) * H_DIM))[tid];
#pragma unroll
            for (int i = 0; i < 16; i++) ffma2(acc[i], w2, s_p[i][dd]);
        }
        __syncthreads();
    }
#pragma unroll
    for (int i = 0; i < 16; i++)
        ((u64*)(g_M + (size_t)(base + i) * H_DIM))[tid] = acc[i];
    int wid = tid >> 5, lane = tid & 31;
    if (wid < 16) {
        int pb = base + wid;
        float s = 0.f;
        for (int d = lane; d < PD; d += 32)
            s += post[(size_t)pb * PD + d] * bq[d];
#pragma unroll
        for (int o = 16; o > 0; o >>= 1)
            s += __shfl_xor_sync(0xffffffffu, s, o);
        if (lane == 0) g_PB[pb] = s;
    }
}

// ---------------- gates chunk prefetch (bulk TMA, warp 0) ----------------
// ch 0-7: h part (Whh_p, x=g_Hb, kc=ch); ch 8-15: i part (Wih_p; kc<4 xt else ctx)
__device__ __forceinline__ void prefetch_mma(
    char* smem, unsigned smem_u32, int buf, int ch, int t,
    const u64* __restrict__ hbcur,
    int jbase, int half, int wid, int lane)
{
    if (wid != 0) return;
    unsigned mbar = smem_u32 + OFF_MB + buf * 8;
    if (lane == 0) mbar_expect(mbar, CHUNK_TX);
    __syncwarp();

    int part_h = (ch < 8);
    int kc = part_h ? ch : (ch - 8);
    const uint4* Wp = part_h ? g_Whh_p : g_Wih_p;
    char* wd = smem + OFF_W + buf * WBUF_B;
    char* xd = smem + OFF_X + buf * XBUF_B;

    if (lane < 6) {   // 6 W slots, 4KB each
        int g = lane >> 1, sl = lane & 1;
        int NT = g * 128 + (jbase >> 3) + sl;
        bulkN(wd + lane * 4096, Wp + ((size_t)NT * 64 + kc * 8) * 32, 4096, mbar);
    }
    {                 // 32 x rows, 512B each (128 split elems)
        int gb = half * 32 + lane;
        const u64* src;
        if (part_h)      src = hbcur + (size_t)gb * (H_DIM / 2) + kc * 64;
        else if (kc < 4) src = g_INCb + ((size_t)t * B_SZ + gb) * (E_DIM / 2) + kc * 64;
        else             src = g_CTXb + (size_t)gb * (PD / 2) + (kc - 4) * 64;
        bulkN(xd + lane * 544, src, 512, mbar);
    }
}

// ---------------- one chunk of split-bf16 MMA ----------------
__device__ __forceinline__ void chunk_mma(
    const u64* s_x_, const uint4* s_w_, int ks, int mt, int nt, int lane,
    float (&acc)[3][4])
{
    const int r0 = mt * 16 + (lane >> 2);
    const int kp = lane & 3;
#pragma unroll
    for (int k16i = 0; k16i < 2; k16i++) {
        int k16 = ks * 2 + k16i;
        u64 xA = s_x_[r0 * XROW_U64 + k16 * 8 + kp];
        u64 xB = s_x_[(r0 + 8) * XROW_U64 + k16 * 8 + kp];
        u64 xC = s_x_[r0 * XROW_U64 + k16 * 8 + kp + 4];
        u64 xD = s_x_[(r0 + 8) * XROW_U64 + k16 * 8 + kp + 4];
        unsigned a0m = (unsigned)xA, a0r = (unsigned)(xA >> 32);
        unsigned a1m = (unsigned)xB, a1r = (unsigned)(xB >> 32);
        unsigned a2m = (unsigned)xC, a2r = (unsigned)(xC >> 32);
        unsigned a3m = (unsigned)xD, a3r = (unsigned)(xD >> 32);
#pragma unroll
        for (int i = 0; i < 3; i++) {
            uint4 wv = s_w_[((nt * 3 + i) * 8 + k16) * 32 + lane];
            mma16(acc[i], a0m, a1m, a2m, a3m, wv.x, wv.y);   // main x main
            mma16(acc[i], a0m, a1m, a2m, a3m, wv.z, wv.w);   // main x resid
            mma16(acc[i], a0r, a1r, a2r, a3r, wv.x, wv.y);   // resid x main
        }
    }
}

// ---------------- persistent recurrent kernel ----------------
__global__ void __launch_bounds__(NTHR, 1) gru_kernel(
    const float* __restrict__ post,
    const float* __restrict__ bih,
    const float* __restrict__ bhh,
    const int* __restrict__ length,
    const int* __restrict__ post_length,
    float* __restrict__ out,
    int write_last)
{
    extern __shared__ __align__(16) char smem[];
    float* s_red = (float*)(smem + OFF_RED);   // [8][48][33]
    float* s_h  = (float*)(smem + OFF_H);
    float* s_sc = (float*)(smem + OFF_SC);
    u64*   s_e2 = (u64*)(smem + OFF_E2);
    u64*   s_pt = (u64*)(smem + OFF_PT);
    float* s_st = (float*)(smem + OFF_ST);
    unsigned smem_u32 = (unsigned)__cvta_generic_to_shared(smem);

    const int tid = threadIdx.x;
    const int bx = blockIdx.x;
    const int wid = tid >> 5;
    const int lane = tid & 31;

    // gates constants
    const int g_half  = bx & 1;
    const int g_jbase = (bx >> 1) * 16;
    const int ks = wid & 3;
    const int mt = (wid >> 2) & 1;
    const int nt = wid >> 3;
    // epilogue mapping: thread = (j, b)
    const int e_j = tid >> 5;
    const int e_b = tid & 31;
    const int e_gb = g_half * 32 + e_b;
    const int e_gj = g_jbase + e_j;
    const int e_len = length[e_gb];

    const int is_attn = (bx < B_SZ);
    const int a_b = bx;

    if (tid == 0) {
        mbar_init(smem_u32 + OFF_MB + 0, 1);
        mbar_init(smem_u32 + OFF_MB + 8, 1);
        asm volatile("fence.proxy.async.shared::cta;" ::: "memory");
    }
    __syncthreads();

    for (int t = 0; t < S_LEN; t++) {
        const float* hcur = g_H[t & 1];
        float* hnext      = g_H[(t & 1) ^ 1];
        const u64* hbcur  = g_Hb[t & 1];
        u64* hbnext       = g_Hb[(t & 1) ^ 1];

        prefetch_mma(smem, smem_u32, 0, 0, t, hbcur, g_jbase, g_half, wid, lane);
        prefetch_mma(smem, smem_u32, 1, 1, t, hbcur, g_jbase, g_half, wid, lane);

        // ============ Attention (blocks 0..63) ============
        if (is_attn) {
            const int b = a_b;
            int pl = post_length[b];
            {
                const float4* src = (const float4*)(hcur + (size_t)b * H_DIM);
                float4* dst = (float4*)s_h;
                if (tid < 256) dst[tid] = src[tid];
            }
            if (tid < PL && tid >= pl) s_sc[tid] = -1e30f;   // masked fill
            __syncthreads();

            const ulonglong2* hh = (const ulonglong2*)s_h;
            for (int p = wid; p < pl; p += 16) {             // only live rows
                const ulonglong2* mm =
                    (const ulonglong2*)(g_M + ((size_t)p * B_SZ + b) * H_DIM);
                u64 a0 = 0ull, a1 = 0ull;
#pragma unroll
                for (int s = lane; s < H_DIM / 4; s += 32) {
                    ulonglong2 mv = mm[s];
                    ulonglong2 hv = hh[s];
                    ffma2(a0, mv.x, hv.x);
                    ffma2(a1, mv.y, hv.y);
                }
                float sres = sum2(a0) + sum2(a1);
#pragma unroll
                for (int o = 16; o > 0; o >>= 1)
                    sres += __shfl_xor_sync(0xffffffffu, sres, o);
                if (lane == 0) s_sc[p] = sres + g_PB[p * B_SZ + b];
            }
            __syncthreads();

            if (tid < 32) {
                float m = -1e30f;
                for (int p = tid; p < PL; p += 32) m = fmaxf(m, s_sc[p]);
#pragma unroll
                for (int o = 16; o > 0; o >>= 1)
                    m = fmaxf(m, __shfl_xor_sync(0xffffffffu, m, o));
                if (tid == 0) s_st[0] = m;
            }
            __syncthreads();
            if (tid < PL) {
                float e = (tid < pl) ? __expf(s_sc[tid] - s_st[0]) : 0.f;
                s_sc[tid] = e;
                float2 ee = make_float2(e, e);
                s_e2[tid] = *(u64*)&ee;
            }
            __syncthreads();
            if (tid < 32) {
                float s = 0.f;
                for (int p = tid; p < PL; p += 32) s += s_sc[p];
#pragma unroll
                for (int o = 16; o > 0; o >>= 1)
                    s += __shfl_xor_sync(0xffffffffu, s, o);
                if (tid == 0) s_st[1] = 1.f / s;
            }
            __syncthreads();

            int plr = (pl + 1) & ~1;                         // even round-up
            {
                int pg = tid >> 8;
                int dp = tid & 255;
                const u64* pb_ = (const u64*)post + (size_t)b * (PD / 2) + dp;
                u64 c0 = 0ull, c1 = 0ull;
                for (int p = pg * 2; p < plr; p += 4) {
                    ffma2(c0, s_e2[p],     pb_[(size_t)p * (B_SZ * PD / 2)]);
                    ffma2(c1, s_e2[p + 1], pb_[(size_t)(p + 1) * (B_SZ * PD / 2)]);
                }
                u64 c2;
                asm("add.rn.f32x2 %0, %1, %2;" : "=l"(c2) : "l"(c0), "l"(c1));
                s_pt[pg * 256 + dp] = c2;
            }
            __syncthreads();
            if (tid < 256) {
                float inv = s_st[1];
                u64 v0 = s_pt[tid], v1 = s_pt[256 + tid];
                float lo = (__int_as_float((unsigned)(v0 & 0xffffffffULL)) +
                            __int_as_float((unsigned)(v1 & 0xffffffffULL))) * inv;
                float hi = (__int_as_float((unsigned)(v0 >> 32)) +
                            __int_as_float((unsigned)(v1 >> 32))) * inv;
                g_CTXb[(size_t)b * (PD / 2) + tid] = split2(lo, hi);
            }
            __syncthreads();
            if (tid == 0) {
                __threadfence();
                unsigned arrived = atomicAdd(&g_countC, 1u) + 1u;
                if (arrived == 64u * (unsigned)(t + 1))
                    atomicExch(&g_releaseC, (unsigned)(t + 1));
            }
        }

        // ================= Gates: split-bf16 mma, TMA double-buffered =================
        {
            float accH[3][4], accI[3][4];
#pragma unroll
            for (int i = 0; i < 3; i++)
#pragma unroll
                for (int r = 0; r < 4; r++) { accH[i][r] = 0.f; accI[i][r] = 0.f; }

            for (int ch = 0; ch < 16; ch++) {
                int buf = ch & 1;
                unsigned parity = (ch >> 1) & 1;
                mbar_wait(smem_u32 + OFF_MB + buf * 8, parity);

                const u64* s_x_ = (const u64*)(smem + OFF_X + buf * XBUF_B);
                const uint4* s_w_ = (const uint4*)(smem + OFF_W + buf * WBUF_B);
                if (ch < 8) chunk_mma(s_x_, s_w_, ks, mt, nt, lane, accH);
                else        chunk_mma(s_x_, s_w_, ks, mt, nt, lane, accI);
                __syncthreads();

                if (ch + 2 < 16) {
                    if (ch == 10 && wid == 0) {   // ctx ready before chunk 12 prefetch
                        while (*(volatile unsigned int*)&g_releaseC <
                               (unsigned)(t + 1)) {
                            __nanosleep(40);
                        }
                        __syncwarp();
                    }
                    prefetch_mma(smem, smem_u32, buf, ch + 2, t, hbcur,
                                 g_jbase, g_half, wid, lane);
                }
            }

            // ---- k-split reduction through smem ----
#pragma unroll
            for (int i = 0; i < 3; i++)
#pragma unroll
                for (int r = 0; r < 4; r++) {
                    int row = (nt * 3 + i) * 8 + (lane & 3) * 2 + (r & 1);
                    int bb  = mt * 16 + (lane >> 2) + (r >> 1) * 8;
                    s_red[((ks * 2 + 0) * 48 + row) * 33 + bb] = accI[i][r];
                    s_red[((ks * 2 + 1) * 48 + row) * 33 + bb] = accH[i][r];
                }
            __syncthreads();

            // ---- epilogue: thread = (j, b) ----
            float gi_[3], gh_[3];
#pragma unroll
            for (int g = 0; g < 3; g++) {
                int row = (g * 2 + (e_j >> 3)) * 8 + (e_j & 7);
                float si = 0.f, sh = 0.f;
#pragma unroll
                for (int kk = 0; kk < 4; kk++) {
                    si += s_red[((kk * 2 + 0) * 48 + row) * 33 + e_b];
                    sh += s_red[((kk * 2 + 1) * 48 + row) * 33 + e_b];
                }
                gi_[g] = si;
                gh_[g] = sh;
            }
            float hp  = hcur[(size_t)e_gb * H_DIM + e_gj];
            float ir  = gi_[0] + bih[e_gj];
            float iz  = gi_[1] + bih[H_DIM + e_gj];
            float inn = gi_[2] + bih[2 * H_DIM + e_gj];
            float hr  = gh_[0] + bhh[e_gj];
            float hz  = gh_[1] + bhh[H_DIM + e_gj];
            float hnn = gh_[2] + bhh[2 * H_DIM + e_gj];
            float r = 1.f / (1.f + __expf(-(ir + hr)));
            float z = 1.f / (1.f + __expf(-(iz + hz)));
            float n = tanhf(inn + r * hnn);
            float hn = (1.f - z) * n + z * hp;
            if (e_len <= t) hn = 0.f;

            hnext[(size_t)e_gb * H_DIM + e_gj] = hn;
            // split-bf16 write (two u16 halves of the pair u64)
            {
                unsigned short m16, r16;
                asm("cvt.rn.bf16.f32 %0, %1;" : "=h"(m16) : "f"(hn));
                float mf = __uint_as_float((unsigned)m16 << 16);
                float rr = hn - mf;
                asm("cvt.rn.bf16.f32 %0, %1;" : "=h"(r16) : "f"(rr));
                unsigned short* hb = (unsigned short*)
                    (hbnext + (((size_t)e_gb * H_DIM + e_gj) >> 1));
                int odd = e_gj & 1;
                hb[odd] = m16;
                hb[2 + odd] = r16;
            }
            out[((size_t)t * B_SZ + e_gb) * H_DIM + e_gj] = hn;
            if (write_last && t == S_LEN - 1) {
                out[(size_t)S_LEN * B_SZ * H_DIM + (size_t)e_gb * H_DIM + e_gj] = hn;
            }
        }
        gsync((unsigned)(t + 1));
    }
}

// ---------------- launch ----------------
extern "C" void kernel_launch(void* const* d_in, const int* in_sizes, int n_in,
                              void* d_out, int out_size) {
    const float* incoming    = (const float*)d_in[0];
    const float* post        = (const float*)d_in[1];
    const float* h_init      = (const float*)d_in[2];
    const float* wih         = (const float*)d_in[3];
    const float* whh         = (const float*)d_in[4];
    const float* bih         = (const float*)d_in[5];
    const float* bhh         = (const float*)d_in[6];
    const float* wq          = (const float*)d_in[7];
    const float* bq          = (const float*)d_in[8];
    const int*   length      = (const int*)d_in[9];
    const int*   post_length = (const int*)d_in[10];
    float* out = (float*)d_out;

    int write_last = (out_size >= S_LEN * B_SZ * H_DIM + B_SZ * H_DIM) ? 1 : 0;

    cudaFuncSetAttribute(gru_kernel, cudaFuncAttributeMaxDynamicSharedMemorySize,
                         SMEM_SZ);

    pre_kernel<<<B_SZ, 256>>>(h_init);
    prep_inc<<<S_LEN, 256>>>(incoming);
    prep_W<<<(2 * 384 * 64 * 32) / 256, 256>>>(wih, whh);
    prep_M<<<(PL * B_SZ) / 16, 512>>>(post, wq, bq);
    gru_kernel<<<NBLK, NTHR, SMEM_SZ>>>(post, bih, bhh,
                                        length, post_length, out, write_last);
}

// round 17
// speedup vs baseline: 1.5453x; 1.0263x over previous
#include <cuda_runtime.h>
#include <cuda_bf16.h>

#define S_LEN 128
#define B_SZ  64
#define E_DIM 512
#define PL    160
#define PD    512
#define H_DIM 1024

#define NBLK 128
#define NTHR 512

typedef unsigned long long u64;

// ---------------- persistent scratch (device globals) ----------------
__device__ __align__(16) float g_H[2][B_SZ * H_DIM];     // fp32 h (attention + epilogue)
__device__ __align__(16) u64 g_Hb[2][B_SZ * H_DIM / 2];  // split-bf16 h (gates)
__device__ __align__(16) u64 g_CTXb[B_SZ * PD / 2];      // split-bf16 ctx
__device__ __align__(16) u64 g_INCb[(size_t)S_LEN * B_SZ * E_DIM / 2];
__device__ __align__(16) float g_M[(size_t)PL * B_SZ * H_DIM];  // 42MB
__device__ __align__(16) float g_PB[PL * B_SZ];
// W packed bf16-split B-fragments: [NT(384)][k16(64)][lane(32)] {b0m,b1m,b0r,b1r}
__device__ __align__(16) uint4 g_Wih_p[(size_t)384 * 64 * 32];
__device__ __align__(16) uint4 g_Whh_p[(size_t)384 * 64 * 32];
__device__ unsigned int g_count;
__device__ unsigned int g_release;
__device__ unsigned int g_countC;
__device__ unsigned int g_releaseC;

// ---------------- smem layout (bytes); 3-stage pipeline ----------------
#define WBUF_B  24576                  // 6 slots x 4KB
#define XROW_U64 68                    // 544B row stride
#define XBUF_B  17408                  // 32 rows x 544B
#define OFF_W   0                      // 3 x 24576 = 73728
#define OFF_X   73728                  // 3 x 17408 = 52224 -> 125952
#define OFF_RED 125952                 // 8 x 48 x 33 floats = 50688 -> 176640
#define OFF_H   176640                 // 4096
#define OFF_SC  180736                 // 640
#define OFF_E2  181376                 // 1280
#define OFF_PT  182656                 // 4096
#define OFF_ST  186752                 // 16
#define OFF_MB  186768                 // 24 (3 mbarriers)
#define SMEM_SZ 186880

#define CHUNK_TX 40960u                // 6*4096 W + 32*512 x

// ---------------- packed f32x2 helpers ----------------
__device__ __forceinline__ void ffma2(u64& d, u64 a, u64 b) {
    asm("fma.rn.f32x2 %0, %1, %2, %0;" : "+l"(d) : "l"(a), "l"(b));
}
__device__ __forceinline__ float sum2(u64 v) {
    float lo = __int_as_float((unsigned)(v & 0xffffffffULL));
    float hi = __int_as_float((unsigned)(v >> 32));
    return lo + hi;
}

// ---------------- bf16 split helpers ----------------
__device__ __forceinline__ u64 split2(float a, float b) {
    unsigned mp;
    asm("cvt.rn.bf16x2.f32 %0, %1, %2;" : "=r"(mp) : "f"(b), "f"(a));
    float ra = a - __uint_as_float(mp << 16);
    float rb = b - __uint_as_float(mp & 0xffff0000u);
    unsigned rp;
    asm("cvt.rn.bf16x2.f32 %0, %1, %2;" : "=r"(rp) : "f"(rb), "f"(ra));
    return ((u64)rp << 32) | (u64)mp;
}
__device__ __forceinline__ void mma16(float (&c)[4],
    unsigned a0, unsigned a1, unsigned a2, unsigned a3,
    unsigned b0, unsigned b1)
{
    asm volatile(
        "mma.sync.aligned.m16n8k16.row.col.f32.bf16.bf16.f32 "
        "{%0,%1,%2,%3}, {%4,%5,%6,%7}, {%8,%9}, {%0,%1,%2,%3};"
        : "+f"(c[0]), "+f"(c[1]), "+f"(c[2]), "+f"(c[3])
        : "r"(a0), "r"(a1), "r"(a2), "r"(a3), "r"(b0), "r"(b1));
}

// ---------------- bulk TMA + mbarrier ----------------
__device__ __forceinline__ void bulkN(void* sdst, const void* gsrc,
                                      unsigned bytes, unsigned mbar) {
    unsigned sd = (unsigned)__cvta_generic_to_shared(sdst);
    asm volatile(
        "cp.async.bulk.shared::cluster.global.mbarrier::complete_tx::bytes "
        "[%0], [%1], %2, [%3];"
        :: "r"(sd), "l"(gsrc), "r"(bytes), "r"(mbar) : "memory");
}
__device__ __forceinline__ void mbar_init(unsigned mbar, unsigned cnt) {
    asm volatile("mbarrier.init.shared.b64 [%0], %1;" :: "r"(mbar), "r"(cnt) : "memory");
}
__device__ __forceinline__ void mbar_expect(unsigned mbar, unsigned tx) {
    asm volatile("mbarrier.arrive.expect_tx.shared.b64 _, [%0], %1;"
                 :: "r"(mbar), "r"(tx) : "memory");
}
__device__ __forceinline__ void mbar_wait(unsigned mbar, unsigned parity) {
    asm volatile(
        "{\n\t"
        ".reg .pred P1;\n\t"
        "WAIT_LOOP_%=:\n\t"
        "mbarrier.try_wait.parity.acquire.cta.shared::cta.b64 P1, [%0], %1, 0x989680;\n\t"
        "@P1 bra.uni WAIT_DONE_%=;\n\t"
        "bra.uni WAIT_LOOP_%=;\n\t"
        "WAIT_DONE_%=:\n\t"
        "}"
        :: "r"(mbar), "r"(parity) : "memory");
}

// ---------------- grid-wide epoch barrier ----------------
__device__ __forceinline__ void gsync(unsigned int epoch) {
    __syncthreads();
    if (threadIdx.x == 0) {
        __threadfence();
        unsigned int arrived = atomicAdd(&g_count, 1u) + 1u;
        if (arrived == (unsigned)NBLK * epoch) {
            atomicExch(&g_release, epoch);
        } else {
            while (*(volatile unsigned int*)&g_release < epoch) {
                __nanosleep(40);
            }
        }
        __threadfence();
    }
    __syncthreads();
}

// ---------------- pre-pass ----------------
__global__ void pre_kernel(const float* __restrict__ h_init) {
    int b = blockIdx.x;
    for (int k = threadIdx.x; k < H_DIM; k += 256)
        g_H[0][b * H_DIM + k] = h_init[k];
    for (int k2 = threadIdx.x; k2 < H_DIM / 2; k2 += 256)
        g_Hb[0][b * (H_DIM / 2) + k2] = split2(h_init[2 * k2], h_init[2 * k2 + 1]);
    if (b == 0 && threadIdx.x == 0) {
        g_count = 0u; g_release = 0u;
        g_countC = 0u; g_releaseC = 0u;
    }
}

__global__ void prep_inc(const float* __restrict__ incoming) {
    int t = blockIdx.x;
    for (int idx = threadIdx.x; idx < B_SZ * E_DIM / 2; idx += 256) {
        const float* src = incoming + (size_t)t * B_SZ * E_DIM + 2 * idx;
        g_INCb[(size_t)t * (B_SZ * E_DIM / 2) + idx] = split2(src[0], src[1]);
    }
}

// ---------------- W bf16-split B-fragment precompute ----------------
__global__ void prep_W(const float* __restrict__ wih,
                       const float* __restrict__ whh) {
    size_t gid = (size_t)blockIdx.x * 256 + threadIdx.x;
    int lane = (int)(gid & 31);
    size_t rest = gid >> 5;
    int k16 = (int)(rest & 63);
    rest >>= 6;
    int NT = (int)(rest % 384);
    int mat = (int)(rest / 384);
    const float* W = mat ? whh : wih;
    uint4* dst = mat ? g_Whh_p : g_Wih_p;
    int R = NT * 8 + (lane >> 2);
    int k0 = k16 * 16 + (lane & 3) * 2;
    float w00 = W[(size_t)R * 1024 + k0];
    float w01 = W[(size_t)R * 1024 + k0 + 1];
    float w10 = W[(size_t)R * 1024 + k0 + 8];
    float w11 = W[(size_t)R * 1024 + k0 + 9];
    u64 s0 = split2(w00, w01);
    u64 s1 = split2(w10, w11);
    uint4 v;
    v.x = (unsigned)s0;
    v.y = (unsigned)s1;
    v.z = (unsigned)(s0 >> 32);
    v.w = (unsigned)(s1 >> 32);
    dst[((size_t)NT * 64 + k16) * 32 + lane] = v;
}

// ---------------- prep_M: tiled GEMM  M[pb,k] = post[pb,:] @ wq[:,k] ----------------
__global__ void __launch_bounds__(256, 2) prep_Mt(
    const float* __restrict__ post, const float* __restrict__ wq)
{
    __shared__ float As[16][130];
    __shared__ u64 Bs[16][66];
    const int tid = threadIdx.x;
    const int pb0 = blockIdx.x * 128;
    const int n0  = blockIdx.y * 128;
    const int mbase = (tid >> 5) * 16 + ((tid & 31) >> 4) * 8;
    const int nub = tid & 15;

    u64 acc[8][4];
#pragma unroll
    for (int r = 0; r < 8; r++)
#pragma unroll
        for (int j = 0; j < 4; j++) acc[r][j] = 0ull;

    for (int k0 = 0; k0 < PD; k0 += 16) {
#pragma unroll
        for (int i = 0; i < 8; i++) {
            int lin = tid + i * 256;
            int m = lin >> 4, k = lin & 15;
            As[k][m] = post[(size_t)(pb0 + m) * PD + k0 + k];
        }
#pragma unroll
        for (int i = 0; i < 4; i++) {
            int lin = tid + i * 256;
            int k = lin >> 6, nu = lin & 63;
            Bs[k][nu] = *(const u64*)(wq + (size_t)(k0 + k) * H_DIM + n0 + 2 * nu);
        }
        __syncthreads();
#pragma unroll
        for (int kk = 0; kk < 16; kk++) {
            u64 a2[8];
#pragma unroll
            for (int r = 0; r < 8; r++) {
                unsigned av = __float_as_uint(As[kk][mbase + r]);
                asm("mov.b64 %0, {%1, %1};" : "=l"(a2[r]) : "r"(av));
            }
#pragma unroll
            for (int j = 0; j < 4; j++) {
                u64 bv = Bs[kk][nub + 16 * j];
#pragma unroll
                for (int r = 0; r < 8; r++) ffma2(acc[r][j], a2[r], bv);
            }
        }
        __syncthreads();
    }
#pragma unroll
    for (int r = 0; r < 8; r++)
#pragma unroll
        for (int j = 0; j < 4; j++)
            ((u64*)(g_M + (size_t)(pb0 + mbase + r) * H_DIM + n0))[nub + 16 * j] =
                acc[r][j];
}

__global__ void prep_PB(const float* __restrict__ post, const float* __restrict__ bq) {
    const int base = blockIdx.x * 16;
    int wid = threadIdx.x >> 5, lane = threadIdx.x & 31;
    int pb = base + wid;
    float s = 0.f;
    for (int d = lane; d < PD; d += 32)
        s += post[(size_t)pb * PD + d] * bq[d];
#pragma unroll
    for (int o = 16; o > 0; o >>= 1)
        s += __shfl_xor_sync(0xffffffffu, s, o);
    if (lane == 0) g_PB[pb] = s;
}

// ---------------- gates chunk prefetch (bulk TMA, warp 0) ----------------
// ch 0-7: h part (Whh_p, x=g_Hb, kc=ch); ch 8-15: i part (Wih_p; kc<4 xt else ctx)
__device__ __forceinline__ void prefetch_mma(
    char* smem, unsigned smem_u32, int buf, int ch, int t,
    const u64* __restrict__ hbcur,
    int jbase, int half, int wid, int lane)
{
    if (wid != 0) return;
    unsigned mbar = smem_u32 + OFF_MB + buf * 8;
    if (lane == 0) mbar_expect(mbar, CHUNK_TX);
    __syncwarp();

    int part_h = (ch < 8);
    int kc = part_h ? ch : (ch - 8);
    const uint4* Wp = part_h ? g_Whh_p : g_Wih_p;
    char* wd = smem + OFF_W + buf * WBUF_B;
    char* xd = smem + OFF_X + buf * XBUF_B;

    if (lane < 6) {
        int g = lane >> 1, sl = lane & 1;
        int NT = g * 128 + (jbase >> 3) + sl;
        bulkN(wd + lane * 4096, Wp + ((size_t)NT * 64 + kc * 8) * 32, 4096, mbar);
    }
    {
        int gb = half * 32 + lane;
        const u64* src;
        if (part_h)      src = hbcur + (size_t)gb * (H_DIM / 2) + kc * 64;
        else if (kc < 4) src = g_INCb + ((size_t)t * B_SZ + gb) * (E_DIM / 2) + kc * 64;
        else             src = g_CTXb + (size_t)gb * (PD / 2) + (kc - 4) * 64;
        bulkN(xd + lane * 544, src, 512, mbar);
    }
}

// ---------------- one chunk of split-bf16 MMA ----------------
__device__ __forceinline__ void chunk_mma(
    const u64* s_x_, const uint4* s_w_, int ks, int mt, int nt, int lane,
    float (&acc)[3][4])
{
    const int r0 = mt * 16 + (lane >> 2);
    const int kp = lane & 3;
#pragma unroll
    for (int k16i = 0; k16i < 2; k16i++) {
        int k16 = ks * 2 + k16i;
        u64 xA = s_x_[r0 * XROW_U64 + k16 * 8 + kp];
        u64 xB = s_x_[(r0 + 8) * XROW_U64 + k16 * 8 + kp];
        u64 xC = s_x_[r0 * XROW_U64 + k16 * 8 + kp + 4];
        u64 xD = s_x_[(r0 + 8) * XROW_U64 + k16 * 8 + kp + 4];
        unsigned a0m = (unsigned)xA, a0r = (unsigned)(xA >> 32);
        unsigned a1m = (unsigned)xB, a1r = (unsigned)(xB >> 32);
        unsigned a2m = (unsigned)xC, a2r = (unsigned)(xC >> 32);
        unsigned a3m = (unsigned)xD, a3r = (unsigned)(xD >> 32);
#pragma unroll
        for (int i = 0; i < 3; i++) {
            uint4 wv = s_w_[((nt * 3 + i) * 8 + k16) * 32 + lane];
            mma16(acc[i], a0m, a1m, a2m, a3m, wv.x, wv.y);
            mma16(acc[i], a0m, a1m, a2m, a3m, wv.z, wv.w);
            mma16(acc[i], a0r, a1r, a2r, a3r, wv.x, wv.y);
        }
    }
}

// ---------------- persistent recurrent kernel ----------------
__global__ void __launch_bounds__(NTHR, 1) gru_kernel(
    const float* __restrict__ post,
    const float* __restrict__ bih,
    const float* __restrict__ bhh,
    const int* __restrict__ length,
    const int* __restrict__ post_length,
    float* __restrict__ out,
    int write_last)
{
    extern __shared__ __align__(16) char smem[];
    float* s_red = (float*)(smem + OFF_RED);
    float* s_h  = (float*)(smem + OFF_H);
    float* s_sc = (float*)(smem + OFF_SC);
    u64*   s_e2 = (u64*)(smem + OFF_E2);
    u64*   s_pt = (u64*)(smem + OFF_PT);
    float* s_st = (float*)(smem + OFF_ST);
    unsigned smem_u32 = (unsigned)__cvta_generic_to_shared(smem);

    const int tid = threadIdx.x;
    const int bx = blockIdx.x;
    const int wid = tid >> 5;
    const int lane = tid & 31;

    const int g_half  = bx & 1;
    const int g_jbase = (bx >> 1) * 16;
    const int ks = wid & 3;
    const int mt = (wid >> 2) & 1;
    const int nt = wid >> 3;
    const int e_j = tid >> 5;
    const int e_b = tid & 31;
    const int e_gb = g_half * 32 + e_b;
    const int e_gj = g_jbase + e_j;
    const int e_len = length[e_gb];

    const int is_attn = (bx < B_SZ);
    const int a_b = bx;

    if (tid == 0) {
        mbar_init(smem_u32 + OFF_MB + 0, 1);
        mbar_init(smem_u32 + OFF_MB + 8, 1);
        mbar_init(smem_u32 + OFF_MB + 16, 1);
        asm volatile("fence.proxy.async.shared::cta;" ::: "memory");
    }
    __syncthreads();

    for (int t = 0; t < S_LEN; t++) {
        const float* hcur = g_H[t & 1];
        float* hnext      = g_H[(t & 1) ^ 1];
        const u64* hbcur  = g_Hb[t & 1];
        u64* hbnext       = g_Hb[(t & 1) ^ 1];

        // prime 3-deep pipeline (h-part chunks; no ctx dependency)
        prefetch_mma(smem, smem_u32, 0, 0, t, hbcur, g_jbase, g_half, wid, lane);
        prefetch_mma(smem, smem_u32, 1, 1, t, hbcur, g_jbase, g_half, wid, lane);
        prefetch_mma(smem, smem_u32, 2, 2, t, hbcur, g_jbase, g_half, wid, lane);

        // ============ Attention (blocks 0..63) ============
        if (is_attn) {
            const int b = a_b;
            int pl = post_length[b];
            {
                const float4* src = (const float4*)(hcur + (size_t)b * H_DIM);
                float4* dst = (float4*)s_h;
                if (tid < 256) dst[tid] = src[tid];
            }
            if (tid < PL && tid >= pl) s_sc[tid] = -1e30f;
            __syncthreads();

            const ulonglong2* hh = (const ulonglong2*)s_h;
            for (int p = wid; p < pl; p += 16) {
                const ulonglong2* mm =
                    (const ulonglong2*)(g_M + ((size_t)p * B_SZ + b) * H_DIM);
                u64 a0 = 0ull, a1 = 0ull;
#pragma unroll
                for (int s = lane; s < H_DIM / 4; s += 32) {
                    ulonglong2 mv = mm[s];
                    ulonglong2 hv = hh[s];
                    ffma2(a0, mv.x, hv.x);
                    ffma2(a1, mv.y, hv.y);
                }
                float sres = sum2(a0) + sum2(a1);
#pragma unroll
                for (int o = 16; o > 0; o >>= 1)
                    sres += __shfl_xor_sync(0xffffffffu, sres, o);
                if (lane == 0) s_sc[p] = sres + g_PB[p * B_SZ + b];
            }
            __syncthreads();

            if (tid < 32) {
                float m = -1e30f;
                for (int p = tid; p < PL; p += 32) m = fmaxf(m, s_sc[p]);
#pragma unroll
                for (int o = 16; o > 0; o >>= 1)
                    m = fmaxf(m, __shfl_xor_sync(0xffffffffu, m, o));
                if (tid == 0) s_st[0] = m;
            }
            __syncthreads();
            if (tid < PL) {
                float e = (tid < pl) ? __expf(s_sc[tid] - s_st[0]) : 0.f;
                s_sc[tid] = e;
                float2 ee = make_float2(e, e);
                s_e2[tid] = *(u64*)&ee;
            }
            __syncthreads();
            if (tid < 32) {
                float s = 0.f;
                for (int p = tid; p < PL; p += 32) s += s_sc[p];
#pragma unroll
                for (int o = 16; o > 0; o >>= 1)
                    s += __shfl_xor_sync(0xffffffffu, s, o);
                if (tid == 0) s_st[1] = 1.f / s;
            }
            __syncthreads();

            int plr8 = (pl + 7) & ~7;       // e2 zero-padded to PL, safe
            {
                int pg = tid >> 8;          // 0/1
                int dp = tid & 255;
                const u64* pb_ = (const u64*)post + (size_t)b * (PD / 2) + dp;
                u64 c0 = 0ull, c1 = 0ull, c2 = 0ull, c3 = 0ull;
                for (int p = pg * 4; p < plr8; p += 8) {
                    ffma2(c0, s_e2[p],     pb_[(size_t)p * (B_SZ * PD / 2)]);
                    ffma2(c1, s_e2[p + 1], pb_[(size_t)(p + 1) * (B_SZ * PD / 2)]);
                    ffma2(c2, s_e2[p + 2], pb_[(size_t)(p + 2) * (B_SZ * PD / 2)]);
                    ffma2(c3, s_e2[p + 3], pb_[(size_t)(p + 3) * (B_SZ * PD / 2)]);
                }
                u64 ca, cb, cc;
                asm("add.rn.f32x2 %0, %1, %2;" : "=l"(ca) : "l"(c0), "l"(c1));
                asm("add.rn.f32x2 %0, %1, %2;" : "=l"(cb) : "l"(c2), "l"(c3));
                asm("add.rn.f32x2 %0, %1, %2;" : "=l"(cc) : "l"(ca), "l"(cb));
                s_pt[pg * 256 + dp] = cc;
            }
            __syncthreads();
            if (tid < 256) {
                float inv = s_st[1];
                u64 v0 = s_pt[tid], v1 = s_pt[256 + tid];
                float lo = (__int_as_float((unsigned)(v0 & 0xffffffffULL)) +
                            __int_as_float((unsigned)(v1 & 0xffffffffULL))) * inv;
                float hi = (__int_as_float((unsigned)(v0 >> 32)) +
                            __int_as_float((unsigned)(v1 >> 32))) * inv;
                g_CTXb[(size_t)b * (PD / 2) + tid] = split2(lo, hi);
            }
            __syncthreads();
            if (tid == 0) {
                __threadfence();
                unsigned arrived = atomicAdd(&g_countC, 1u) + 1u;
                if (arrived == 64u * (unsigned)(t + 1))
                    atomicExch(&g_releaseC, (unsigned)(t + 1));
            }
        }

        // ================= Gates: split-bf16 mma, 3-stage TMA pipeline =================
        {
            float accH[3][4], accI[3][4];
#pragma unroll
            for (int i = 0; i < 3; i++)
#pragma unroll
                for (int r = 0; r < 4; r++) { accH[i][r] = 0.f; accI[i][r] = 0.f; }

            for (int ch = 0; ch < 16; ch++) {
                int buf = ch % 3;
                int u = ch / 3;
                int uses = (buf == 0) ? 6 : 5;
                unsigned parity = ((unsigned)(t * uses + u)) & 1;
                mbar_wait(smem_u32 + OFF_MB + buf * 8, parity);

                const u64* s_x_ = (const u64*)(smem + OFF_X + buf * XBUF_B);
                const uint4* s_w_ = (const uint4*)(smem + OFF_W + buf * WBUF_B);
                if (ch < 8) chunk_mma(s_x_, s_w_, ks, mt, nt, lane, accH);
                else        chunk_mma(s_x_, s_w_, ks, mt, nt, lane, accI);
                __syncthreads();

                if (ch + 3 < 16) {
                    if (ch == 9 && wid == 0) {   // ctx ready before chunk-12 prefetch
                        while (*(volatile unsigned int*)&g_releaseC <
                               (unsigned)(t + 1)) {
                            __nanosleep(40);
                        }
                        __syncwarp();
                    }
                    prefetch_mma(smem, smem_u32, buf, ch + 3, t, hbcur,
                                 g_jbase, g_half, wid, lane);
                }
            }

            // ---- k-split reduction through smem ----
#pragma unroll
            for (int i = 0; i < 3; i++)
#pragma unroll
                for (int r = 0; r < 4; r++) {
                    int row = (nt * 3 + i) * 8 + (lane & 3) * 2 + (r & 1);
                    int bb  = mt * 16 + (lane >> 2) + (r >> 1) * 8;
                    s_red[((ks * 2 + 0) * 48 + row) * 33 + bb] = accI[i][r];
                    s_red[((ks * 2 + 1) * 48 + row) * 33 + bb] = accH[i][r];
                }
            __syncthreads();

            // ---- epilogue: thread = (j, b) ----
            float gi_[3], gh_[3];
#pragma unroll
            for (int g = 0; g < 3; g++) {
                int row = (g * 2 + (e_j >> 3)) * 8 + (e_j & 7);
                float si = 0.f, sh = 0.f;
#pragma unroll
                for (int kk = 0; kk < 4; kk++) {
                    si += s_red[((kk * 2 + 0) * 48 + row) * 33 + e_b];
                    sh += s_red[((kk * 2 + 1) * 48 + row) * 33 + e_b];
                }
                gi_[g] = si;
                gh_[g] = sh;
            }
            float hp  = hcur[(size_t)e_gb * H_DIM + e_gj];
            float ir  = gi_[0] + bih[e_gj];
            float iz  = gi_[1] + bih[H_DIM + e_gj];
            float inn = gi_[2] + bih[2 * H_DIM + e_gj];
            float hr  = gh_[0] + bhh[e_gj];
            float hz  = gh_[1] + bhh[H_DIM + e_gj];
            float hnn = gh_[2] + bhh[2 * H_DIM + e_gj];
            float r = 1.f / (1.f + __expf(-(ir + hr)));
            float z = 1.f / (1.f + __expf(-(iz + hz)));
            float n = tanhf(inn + r * hnn);
            float hn = (1.f - z) * n + z * hp;
            if (e_len <= t) hn = 0.f;

            hnext[(size_t)e_gb * H_DIM + e_gj] = hn;
            {
                unsigned short m16, r16;
                asm("cvt.rn.bf16.f32 %0, %1;" : "=h"(m16) : "f"(hn));
                float mf = __uint_as_float((unsigned)m16 << 16);
                float rr = hn - mf;
                asm("cvt.rn.bf16.f32 %0, %1;" : "=h"(r16) : "f"(rr));
                unsigned short* hb = (unsigned short*)
                    (hbnext + (((size_t)e_gb * H_DIM + e_gj) >> 1));
                int odd = e_gj & 1;
                hb[odd] = m16;
                hb[2 + odd] = r16;
            }
            out[((size_t)t * B_SZ + e_gb) * H_DIM + e_gj] = hn;
            if (write_last && t == S_LEN - 1) {
                out[(size_t)S_LEN * B_SZ * H_DIM + (size_t)e_gb * H_DIM + e_gj] = hn;
            }
        }
        gsync((unsigned)(t + 1));
    }
}

// ---------------- launch ----------------
extern "C" void kernel_launch(void* const* d_in, const int* in_sizes, int n_in,
                              void* d_out, int out_size) {
    const float* incoming    = (const float*)d_in[0];
    const float* post        = (const float*)d_in[1];
    const float* h_init      = (const float*)d_in[2];
    const float* wih         = (const float*)d_in[3];
    const float* whh         = (const float*)d_in[4];
    const float* bih         = (const float*)d_in[5];
    const float* bhh         = (const float*)d_in[6];
    const float* wq          = (const float*)d_in[7];
    const float* bq          = (const float*)d_in[8];
    const int*   length      = (const int*)d_in[9];
    const int*   post_length = (const int*)d_in[10];
    float* out = (float*)d_out;

    int write_last = (out_size >= S_LEN * B_SZ * H_DIM + B_SZ * H_DIM) ? 1 : 0;

    cudaFuncSetAttribute(gru_kernel, cudaFuncAttributeMaxDynamicSharedMemorySize,
                         SMEM_SZ);

    pre_kernel<<<B_SZ, 256>>>(h_init);
    prep_inc<<<S_LEN, 256>>>(incoming);
    prep_W<<<(2 * 384 * 64 * 32) / 256, 256>>>(wih, whh);
    {
        dim3 g(80, 8);
        prep_Mt<<<g, 256>>>(post, wq);
    }
    prep_PB<<<(PL * B_SZ) / 16, 512>>>(post, bq);
    gru_kernel<<<NBLK, NTHR, SMEM_SZ>>>(post, bih, bhh,
                                        length, post_length, out, write_last);
}